// round 4
// baseline (speedup 1.0000x reference)
#include <cuda_runtime.h>

#define LL   2048
#define BB   2
#define DMODEL 512
#define HH   8
#define DKK  64
#define NT   4096   // BB*LL
#define HB   16     // HH*BB
#define KT   16     // k tiles of 128 in scores

// ---------------- scratch (device globals; no allocation allowed) ----------------
__device__ float g_qh[HB * LL * DKK];   // [h*2+b][l][d], pre-scaled by 1/64
__device__ float g_kh[HB * LL * DKK];
__device__ float g_vh[HB * LL * DKK];
__device__ float g_ctxa[NT * DMODEL];   // ctx partial, k-split 0
__device__ float g_ctxb[NT * DMODEL];   // ctx partial, k-split 1
__device__ float g_psum[HB * LL * KT];  // per (row, ktile) sum of exp(S)
__device__ float g_linv[HB * LL];       // 1 / row sumexp

// ---------------- packed f32x2 helpers (sm_100+ FFMA2) ----------------
__device__ __forceinline__ unsigned long long pack2(float x) {
    unsigned long long r;
    asm("mov.b64 %0, {%1, %1};" : "=l"(r) : "f"(x));
    return r;
}
__device__ __forceinline__ void ffma2(unsigned long long& d, unsigned long long a, unsigned long long b) {
    asm("fma.rn.f32x2 %0, %1, %2, %0;" : "+l"(d) : "l"(a), "l"(b));
}
__device__ __forceinline__ float2 unpk(unsigned long long p) {
    float2 r;
    asm("mov.b64 {%0, %1}, %2;" : "=f"(r.x), "=f"(r.y) : "l"(p));
    return r;
}

// =====================================================================
// Kernel 1: fused QKV projection.  Y = (X @ W + b) [* 1/64 for Q]
// =====================================================================
__global__ __launch_bounds__(256) void proj_kernel(
    const float* __restrict__ qin, const float* __restrict__ kin, const float* __restrict__ vin,
    const float* __restrict__ Wq, const float* __restrict__ bq,
    const float* __restrict__ Wk, const float* __restrict__ bk,
    const float* __restrict__ Wv, const float* __restrict__ bv)
{
    __shared__ float As[16][128];   // [k][row]
    __shared__ float Bs[16][128];   // [k][col]

    const int z = blockIdx.z;
    const float* X    = (z == 0) ? qin : (z == 1) ? kin : vin;
    const float* W    = (z == 0) ? Wq  : (z == 1) ? Wk  : Wv;
    const float* bias = (z == 0) ? bq  : (z == 1) ? bk  : bv;
    float* outp       = (z == 0) ? g_qh : (z == 1) ? g_kh : g_vh;
    const float scale = (z == 0) ? (1.0f / 64.0f) : 1.0f;

    const int col0 = blockIdx.x * 128;
    const int row0 = blockIdx.y * 128;
    const int t = threadIdx.x, tx = t & 15, ty = t >> 4;

    unsigned long long acc[8][4];
#pragma unroll
    for (int i = 0; i < 8; i++)
#pragma unroll
        for (int j = 0; j < 4; j++) acc[i][j] = 0ull;

    for (int k0 = 0; k0 < DMODEL; k0 += 16) {
#pragma unroll
        for (int p = 0; p < 2; p++) {
            int fi = t + p * 256;
            int k4 = fi & 3, row = fi >> 2;
            float4 fa = *(const float4*)(X + (size_t)(row0 + row) * DMODEL + k0 + k4 * 4);
            As[k4 * 4 + 0][row] = fa.x; As[k4 * 4 + 1][row] = fa.y;
            As[k4 * 4 + 2][row] = fa.z; As[k4 * 4 + 3][row] = fa.w;
            int c4 = fi & 31, kk = fi >> 5;
            float4 fb = *(const float4*)(W + (size_t)(k0 + kk) * DMODEL + col0 + c4 * 4);
            *(float4*)&Bs[kk][c4 * 4] = fb;
        }
        __syncthreads();
#pragma unroll
        for (int kk = 0; kk < 16; kk++) {
            float a[8];
            *(float4*)&a[0] = *(float4*)&As[kk][ty * 4];
            *(float4*)&a[4] = *(float4*)&As[kk][64 + ty * 4];
            ulonglong2 b0 = *(ulonglong2*)&Bs[kk][tx * 4];
            ulonglong2 b1 = *(ulonglong2*)&Bs[kk][64 + tx * 4];
            unsigned long long bp[4] = {b0.x, b0.y, b1.x, b1.y};
            unsigned long long ad[8];
#pragma unroll
            for (int i = 0; i < 8; i++) ad[i] = pack2(a[i]);
#pragma unroll
            for (int i = 0; i < 8; i++)
#pragma unroll
                for (int j = 0; j < 4; j++) ffma2(acc[i][j], ad[i], bp[j]);
        }
        __syncthreads();
    }

#pragma unroll
    for (int i = 0; i < 8; i++) {
        int row = row0 + ((i < 4) ? ty * 4 + i : 64 + ty * 4 + (i - 4));
        int bidx = row >> 11, l = row & 2047;
#pragma unroll
        for (int jj = 0; jj < 2; jj++) {
            int colb = col0 + (jj ? 64 + tx * 4 : tx * 4);
            int h = colb >> 6, d = colb & 63;
            float2 u0 = unpk(acc[i][jj * 2 + 0]);
            float2 u1 = unpk(acc[i][jj * 2 + 1]);
            float4 o;
            o.x = (u0.x + bias[colb + 0]) * scale;
            o.y = (u0.y + bias[colb + 1]) * scale;
            o.z = (u1.x + bias[colb + 2]) * scale;
            o.w = (u1.y + bias[colb + 3]) * scale;
            *(float4*)(outp + (size_t)((h * BB + bidx) * LL + l) * DKK + d) = o;
        }
    }
}

// =====================================================================
// Kernel 2a: E = exp((Q/64) @ K^T) masked->0, stored in attn region;
//            plus per-(row, ktile) sums of E.
// (Scores are O(1) magnitude here, so exp without max-shift is safe and
//  mathematically identical to softmax.)
// =====================================================================
__global__ __launch_bounds__(256) void scores_kernel(
    const int* __restrict__ mask, float* __restrict__ attn)
{
    __shared__ float As[16][128];   // [d][qrow]
    __shared__ float Bs[16][128];   // [d][krow]

    const int hb = blockIdx.z;
    const int q0 = blockIdx.y * 128;
    const int k0 = blockIdx.x * 128;
    const int kt = blockIdx.x;
    const int b  = hb & 1;
    const float* qh = g_qh + (size_t)hb * LL * DKK;
    const float* kh = g_kh + (size_t)hb * LL * DKK;
    const int t = threadIdx.x, tx = t & 15, ty = t >> 4;

    unsigned long long acc[8][4];
#pragma unroll
    for (int i = 0; i < 8; i++)
#pragma unroll
        for (int j = 0; j < 4; j++) acc[i][j] = 0ull;

    for (int d0 = 0; d0 < DKK; d0 += 16) {
#pragma unroll
        for (int p = 0; p < 2; p++) {
            int fi = t + p * 256;
            int d4 = fi & 3, row = fi >> 2;
            float4 fa = *(const float4*)(qh + (size_t)(q0 + row) * DKK + d0 + d4 * 4);
            As[d4 * 4 + 0][row] = fa.x; As[d4 * 4 + 1][row] = fa.y;
            As[d4 * 4 + 2][row] = fa.z; As[d4 * 4 + 3][row] = fa.w;
            float4 fb = *(const float4*)(kh + (size_t)(k0 + row) * DKK + d0 + d4 * 4);
            Bs[d4 * 4 + 0][row] = fb.x; Bs[d4 * 4 + 1][row] = fb.y;
            Bs[d4 * 4 + 2][row] = fb.z; Bs[d4 * 4 + 3][row] = fb.w;
        }
        __syncthreads();
#pragma unroll
        for (int dd = 0; dd < 16; dd++) {
            float a[8];
            *(float4*)&a[0] = *(float4*)&As[dd][ty * 4];
            *(float4*)&a[4] = *(float4*)&As[dd][64 + ty * 4];
            ulonglong2 b0 = *(ulonglong2*)&Bs[dd][tx * 4];
            ulonglong2 b1 = *(ulonglong2*)&Bs[dd][64 + tx * 4];
            unsigned long long bp[4] = {b0.x, b0.y, b1.x, b1.y};
            unsigned long long ad[8];
#pragma unroll
            for (int i = 0; i < 8; i++) ad[i] = pack2(a[i]);
#pragma unroll
            for (int i = 0; i < 8; i++)
#pragma unroll
                for (int j = 0; j < 4; j++) ffma2(acc[i][j], ad[i], bp[j]);
        }
        __syncthreads();
    }

    float* ab = attn + (size_t)hb * LL * LL;
    const int* mb = mask + (size_t)b * LL * LL;
#pragma unroll
    for (int i = 0; i < 8; i++) {
        int r = q0 + ((i < 4) ? ty * 4 + i : 64 + ty * 4 + (i - 4));
        float rowsum = 0.0f;
#pragma unroll
        for (int jj = 0; jj < 2; jj++) {
            int cb = k0 + (jj ? 64 + tx * 4 : tx * 4);
            int4 mv = *(const int4*)(mb + (size_t)r * LL + cb);
            float2 u0 = unpk(acc[i][jj * 2 + 0]);
            float2 u1 = unpk(acc[i][jj * 2 + 1]);
            float4 e;
            e.x = mv.x ? __expf(u0.x) : 0.0f;
            e.y = mv.y ? __expf(u0.y) : 0.0f;
            e.z = mv.z ? __expf(u1.x) : 0.0f;
            e.w = mv.w ? __expf(u1.y) : 0.0f;
            *(float4*)(ab + (size_t)r * LL + cb) = e;
            rowsum += e.x + e.y + e.z + e.w;
        }
#pragma unroll
        for (int o = 1; o < 16; o <<= 1)
            rowsum += __shfl_xor_sync(0xffffffffu, rowsum, o);
        if (tx == 0)
            g_psum[(size_t)(hb * LL + r) * KT + kt] = rowsum;
    }
}

// =====================================================================
// Kernel 2b: combine tile sums -> 1/rowsum
// =====================================================================
__global__ __launch_bounds__(256) void combine_kernel()
{
    int r = blockIdx.x * 256 + threadIdx.x;   // 32768 rows
    float L = 0.0f;
#pragma unroll
    for (int j = 0; j < KT; j++) L += g_psum[(size_t)r * KT + j];
    g_linv[r] = 1.0f / L;
}

// =====================================================================
// Kernel 2c: P = E * linv (written back) and ctx_part = P@V over k-split.
// 128q x 64d tile, 128 threads, 8x8 microtile with row-pair-packed A.
// A LDS depends only on ty, B LDS only on tx -> smem broadcast dedup.
// =====================================================================
__global__ __launch_bounds__(128) void pv_kernel(float* __restrict__ attn)
{
    __shared__ float Ps[32][132];   // [k][q]
    __shared__ float Vs[32][72];    // [k][d]

    const int hb = blockIdx.y;
    const int q0 = blockIdx.x * 128;
    const int ks = blockIdx.z;
    const int t = threadIdx.x, tx = t & 7, ty = t >> 3;   // tx 0..7 cols, ty 0..15 rows

    float* attnBase = attn + (size_t)hb * LL * LL + (size_t)q0 * LL;
    const float* vhBase = g_vh + (size_t)hb * LL * DKK;
    float* ctxp = ks ? g_ctxb : g_ctxa;

    // load-phase row scales (rows ty + p*16)
    float lrow[8];
#pragma unroll
    for (int p = 0; p < 8; p++)
        lrow[p] = g_linv[hb * LL + q0 + ty + p * 16];

    unsigned long long acc[4][8];   // [row-pair][col]
#pragma unroll
    for (int i = 0; i < 4; i++)
#pragma unroll
        for (int j = 0; j < 8; j++) acc[i][j] = 0ull;

    const int kbeg = ks * (LL / 2);
    const int kend = kbeg + (LL / 2);
    for (int k0 = kbeg; k0 < kend; k0 += 32) {
        // stage 128x32 E tile -> P (write back) -> Ps transposed
#pragma unroll
        for (int p = 0; p < 8; p++) {
            int row = ty + p * 16;
            float* gp = attnBase + (size_t)row * LL + k0 + tx * 4;
            float4 ev = *(const float4*)gp;
            float li = lrow[p];
            float4 pvv = {ev.x * li, ev.y * li, ev.z * li, ev.w * li};
            *(float4*)gp = pvv;
            int c = tx * 4;
            Ps[c + 0][row] = pvv.x; Ps[c + 1][row] = pvv.y;
            Ps[c + 2][row] = pvv.z; Ps[c + 3][row] = pvv.w;
        }
        // stage V 32x64
#pragma unroll
        for (int p = 0; p < 4; p++) {
            int fi = t + p * 128;
            int d4 = fi & 15, kr = fi >> 4;
            float4 f = *(const float4*)(vhBase + (size_t)(k0 + kr) * DKK + d4 * 4);
            *(float4*)&Vs[kr][d4 * 4] = f;
        }
        __syncthreads();
#pragma unroll
        for (int kk = 0; kk < 32; kk++) {
            // A: 8 rows as 4 natural packed pairs (broadcast across tx)
            ulonglong2 A0 = *(ulonglong2*)&Ps[kk][ty * 8];
            ulonglong2 A1 = *(ulonglong2*)&Ps[kk][ty * 8 + 4];
            unsigned long long ap[4] = {A0.x, A0.y, A1.x, A1.y};
            // B: 8 cols, duplicated packs (broadcast across ty)
            float4 b0 = *(float4*)&Vs[kk][tx * 8];
            float4 b1 = *(float4*)&Vs[kk][tx * 8 + 4];
            unsigned long long bp[8] = {pack2(b0.x), pack2(b0.y), pack2(b0.z), pack2(b0.w),
                                        pack2(b1.x), pack2(b1.y), pack2(b1.z), pack2(b1.w)};
#pragma unroll
            for (int i = 0; i < 4; i++)
#pragma unroll
                for (int j = 0; j < 8; j++) ffma2(acc[i][j], ap[i], bp[j]);
        }
        __syncthreads();
    }

    // ctx: rows q0+ty*8+2i(+1), cols h*64 + tx*8..+7
    const int h = hb >> 1, b = hb & 1;
#pragma unroll
    for (int i = 0; i < 4; i++) {
        float lo[8], hi[8];
#pragma unroll
        for (int j = 0; j < 8; j++) {
            float2 u = unpk(acc[i][j]);
            lo[j] = u.x; hi[j] = u.y;
        }
        int row = q0 + ty * 8 + 2 * i;
        float* o0 = ctxp + (size_t)(b * LL + row) * DMODEL + h * 64 + tx * 8;
        float* o1 = o0 + DMODEL;
        *(float4*)o0       = *(float4*)&lo[0];
        *(float4*)(o0 + 4) = *(float4*)&lo[4];
        *(float4*)o1       = *(float4*)&hi[0];
        *(float4*)(o1 + 4) = *(float4*)&hi[4];
    }
}

// =====================================================================
// Kernel 3: out = (ctxa + ctxb) @ Wo + bo + residual(q)
// =====================================================================
__global__ __launch_bounds__(256) void outproj_kernel(
    const float* __restrict__ resid, const float* __restrict__ Wo,
    const float* __restrict__ bo, float* __restrict__ out)
{
    __shared__ float As[16][128];
    __shared__ float Bs[16][128];

    const int col0 = blockIdx.x * 128;
    const int row0 = blockIdx.y * 128;
    const int t = threadIdx.x, tx = t & 15, ty = t >> 4;

    unsigned long long acc[8][4];
#pragma unroll
    for (int i = 0; i < 8; i++)
#pragma unroll
        for (int j = 0; j < 4; j++) acc[i][j] = 0ull;

    for (int k0 = 0; k0 < DMODEL; k0 += 16) {
#pragma unroll
        for (int p = 0; p < 2; p++) {
            int fi = t + p * 256;
            int k4 = fi & 3, row = fi >> 2;
            size_t ia = (size_t)(row0 + row) * DMODEL + k0 + k4 * 4;
            float4 fa = *(const float4*)(g_ctxa + ia);
            float4 f2 = *(const float4*)(g_ctxb + ia);
            As[k4 * 4 + 0][row] = fa.x + f2.x; As[k4 * 4 + 1][row] = fa.y + f2.y;
            As[k4 * 4 + 2][row] = fa.z + f2.z; As[k4 * 4 + 3][row] = fa.w + f2.w;
            int c4 = fi & 31, kk = fi >> 5;
            float4 fb = *(const float4*)(Wo + (size_t)(k0 + kk) * DMODEL + col0 + c4 * 4);
            *(float4*)&Bs[kk][c4 * 4] = fb;
        }
        __syncthreads();
#pragma unroll
        for (int kk = 0; kk < 16; kk++) {
            float a[8];
            *(float4*)&a[0] = *(float4*)&As[kk][ty * 4];
            *(float4*)&a[4] = *(float4*)&As[kk][64 + ty * 4];
            ulonglong2 b0 = *(ulonglong2*)&Bs[kk][tx * 4];
            ulonglong2 b1 = *(ulonglong2*)&Bs[kk][64 + tx * 4];
            unsigned long long bp[4] = {b0.x, b0.y, b1.x, b1.y};
            unsigned long long ad[8];
#pragma unroll
            for (int i = 0; i < 8; i++) ad[i] = pack2(a[i]);
#pragma unroll
            for (int i = 0; i < 8; i++)
#pragma unroll
                for (int j = 0; j < 4; j++) ffma2(acc[i][j], ad[i], bp[j]);
        }
        __syncthreads();
    }

#pragma unroll
    for (int i = 0; i < 8; i++) {
        int row = row0 + ((i < 4) ? ty * 4 + i : 64 + ty * 4 + (i - 4));
#pragma unroll
        for (int jj = 0; jj < 2; jj++) {
            int cb = col0 + (jj ? 64 + tx * 4 : tx * 4);
            float4 rb = *(const float4*)(resid + (size_t)row * DMODEL + cb);
            float4 bb = *(const float4*)(bo + cb);
            float2 u0 = unpk(acc[i][jj * 2 + 0]);
            float2 u1 = unpk(acc[i][jj * 2 + 1]);
            float4 o;
            o.x = u0.x + bb.x + rb.x;
            o.y = u0.y + bb.y + rb.y;
            o.z = u1.x + bb.z + rb.z;
            o.w = u1.y + bb.w + rb.w;
            *(float4*)(out + (size_t)row * DMODEL + cb) = o;
        }
    }
}

// =====================================================================
extern "C" void kernel_launch(void* const* d_in, const int* in_sizes, int n_in,
                              void* d_out, int out_size)
{
    const float* q    = (const float*)d_in[0];
    const float* k    = (const float*)d_in[1];
    const float* v    = (const float*)d_in[2];
    const int*   mask = (const int*)  d_in[3];
    const float* Wq   = (const float*)d_in[4];
    const float* bq   = (const float*)d_in[5];
    const float* Wk   = (const float*)d_in[6];
    const float* bk   = (const float*)d_in[7];
    const float* Wv   = (const float*)d_in[8];
    const float* bv   = (const float*)d_in[9];
    const float* Wo   = (const float*)d_in[10];
    const float* bo   = (const float*)d_in[11];

    float* out  = (float*)d_out;
    float* attn = out + (size_t)NT * DMODEL;

    proj_kernel<<<dim3(4, 32, 3), 256>>>(q, k, v, Wq, bq, Wk, bk, Wv, bv);
    scores_kernel<<<dim3(16, 16, 16), 256>>>(mask, attn);
    combine_kernel<<<128, 256>>>();
    pv_kernel<<<dim3(16, 16, 2), 128>>>(attn);
    outproj_kernel<<<dim3(4, 32), 256>>>(q, Wo, bo, out);
}

// round 5
// speedup vs baseline: 1.2472x; 1.2472x over previous
#include <cuda_runtime.h>

#define LL   2048
#define BB   2
#define DMODEL 512
#define HH   8
#define DKK  64
#define NT   4096   // BB*LL
#define HB   16     // HH*BB
#define KT   16     // k tiles of 128 in scores

// ---------------- scratch (device globals; no allocation allowed) ----------------
__device__ float g_qh[HB * LL * DKK];   // [h*2+b][l][d], pre-scaled by 1/64
__device__ float g_kh[HB * LL * DKK];
__device__ float g_vh[HB * LL * DKK];
__device__ float g_ctxa[NT * DMODEL];   // ctx partial, k-split 0
__device__ float g_ctxb[NT * DMODEL];   // ctx partial, k-split 1
__device__ float g_psum[HB * LL * KT];  // per (row, ktile) sum of exp(S)
__device__ float g_linv[HB * LL];       // 1 / row sumexp

// ---------------- packed f32x2 helpers (sm_100+ FFMA2) ----------------
__device__ __forceinline__ unsigned long long pack2(float x) {
    unsigned long long r;
    asm("mov.b64 %0, {%1, %1};" : "=l"(r) : "f"(x));
    return r;
}
__device__ __forceinline__ void ffma2(unsigned long long& d, unsigned long long a, unsigned long long b) {
    asm("fma.rn.f32x2 %0, %1, %2, %0;" : "+l"(d) : "l"(a), "l"(b));
}
__device__ __forceinline__ float2 unpk(unsigned long long p) {
    float2 r;
    asm("mov.b64 {%0, %1}, %2;" : "=f"(r.x), "=f"(r.y) : "l"(p));
    return r;
}

// =====================================================================
// Kernel 1: fused QKV projection.  Y = (X @ W + b) [* 1/64 for Q]
// =====================================================================
__global__ __launch_bounds__(256) void proj_kernel(
    const float* __restrict__ qin, const float* __restrict__ kin, const float* __restrict__ vin,
    const float* __restrict__ Wq, const float* __restrict__ bq,
    const float* __restrict__ Wk, const float* __restrict__ bk,
    const float* __restrict__ Wv, const float* __restrict__ bv)
{
    __shared__ float As[16][128];   // [k][row]
    __shared__ float Bs[16][128];   // [k][col]

    const int z = blockIdx.z;
    const float* X    = (z == 0) ? qin : (z == 1) ? kin : vin;
    const float* W    = (z == 0) ? Wq  : (z == 1) ? Wk  : Wv;
    const float* bias = (z == 0) ? bq  : (z == 1) ? bk  : bv;
    float* outp       = (z == 0) ? g_qh : (z == 1) ? g_kh : g_vh;
    const float scale = (z == 0) ? (1.0f / 64.0f) : 1.0f;

    const int col0 = blockIdx.x * 128;
    const int row0 = blockIdx.y * 128;
    const int t = threadIdx.x, tx = t & 15, ty = t >> 4;

    unsigned long long acc[8][4];
#pragma unroll
    for (int i = 0; i < 8; i++)
#pragma unroll
        for (int j = 0; j < 4; j++) acc[i][j] = 0ull;

    for (int k0 = 0; k0 < DMODEL; k0 += 16) {
#pragma unroll
        for (int p = 0; p < 2; p++) {
            int fi = t + p * 256;
            int k4 = fi & 3, row = fi >> 2;
            float4 fa = *(const float4*)(X + (size_t)(row0 + row) * DMODEL + k0 + k4 * 4);
            As[k4 * 4 + 0][row] = fa.x; As[k4 * 4 + 1][row] = fa.y;
            As[k4 * 4 + 2][row] = fa.z; As[k4 * 4 + 3][row] = fa.w;
            int c4 = fi & 31, kk = fi >> 5;
            float4 fb = *(const float4*)(W + (size_t)(k0 + kk) * DMODEL + col0 + c4 * 4);
            *(float4*)&Bs[kk][c4 * 4] = fb;
        }
        __syncthreads();
#pragma unroll
        for (int kk = 0; kk < 16; kk++) {
            float a[8];
            *(float4*)&a[0] = *(float4*)&As[kk][ty * 4];
            *(float4*)&a[4] = *(float4*)&As[kk][64 + ty * 4];
            ulonglong2 b0 = *(ulonglong2*)&Bs[kk][tx * 4];
            ulonglong2 b1 = *(ulonglong2*)&Bs[kk][64 + tx * 4];
            unsigned long long bp[4] = {b0.x, b0.y, b1.x, b1.y};
            unsigned long long ad[8];
#pragma unroll
            for (int i = 0; i < 8; i++) ad[i] = pack2(a[i]);
#pragma unroll
            for (int i = 0; i < 8; i++)
#pragma unroll
                for (int j = 0; j < 4; j++) ffma2(acc[i][j], ad[i], bp[j]);
        }
        __syncthreads();
    }

#pragma unroll
    for (int i = 0; i < 8; i++) {
        int row = row0 + ((i < 4) ? ty * 4 + i : 64 + ty * 4 + (i - 4));
        int bidx = row >> 11, l = row & 2047;
#pragma unroll
        for (int jj = 0; jj < 2; jj++) {
            int colb = col0 + (jj ? 64 + tx * 4 : tx * 4);
            int h = colb >> 6, d = colb & 63;
            float2 u0 = unpk(acc[i][jj * 2 + 0]);
            float2 u1 = unpk(acc[i][jj * 2 + 1]);
            float4 o;
            o.x = (u0.x + bias[colb + 0]) * scale;
            o.y = (u0.y + bias[colb + 1]) * scale;
            o.z = (u1.x + bias[colb + 2]) * scale;
            o.w = (u1.y + bias[colb + 3]) * scale;
            *(float4*)(outp + (size_t)((h * BB + bidx) * LL + l) * DKK + d) = o;
        }
    }
}

// =====================================================================
// Kernel 2a: E = exp((Q/64) @ K^T) masked->0, stored in attn region;
//            plus per-(row, ktile) sums of E.
// =====================================================================
__global__ __launch_bounds__(256) void scores_kernel(
    const int* __restrict__ mask, float* __restrict__ attn)
{
    __shared__ float As[16][128];   // [d][qrow]
    __shared__ float Bs[16][128];   // [d][krow]

    const int hb = blockIdx.z;
    const int q0 = blockIdx.y * 128;
    const int k0 = blockIdx.x * 128;
    const int kt = blockIdx.x;
    const int b  = hb & 1;
    const float* qh = g_qh + (size_t)hb * LL * DKK;
    const float* kh = g_kh + (size_t)hb * LL * DKK;
    const int t = threadIdx.x, tx = t & 15, ty = t >> 4;

    unsigned long long acc[8][4];
#pragma unroll
    for (int i = 0; i < 8; i++)
#pragma unroll
        for (int j = 0; j < 4; j++) acc[i][j] = 0ull;

    for (int d0 = 0; d0 < DKK; d0 += 16) {
#pragma unroll
        for (int p = 0; p < 2; p++) {
            int fi = t + p * 256;
            int d4 = fi & 3, row = fi >> 2;
            float4 fa = *(const float4*)(qh + (size_t)(q0 + row) * DKK + d0 + d4 * 4);
            As[d4 * 4 + 0][row] = fa.x; As[d4 * 4 + 1][row] = fa.y;
            As[d4 * 4 + 2][row] = fa.z; As[d4 * 4 + 3][row] = fa.w;
            float4 fb = *(const float4*)(kh + (size_t)(k0 + row) * DKK + d0 + d4 * 4);
            Bs[d4 * 4 + 0][row] = fb.x; Bs[d4 * 4 + 1][row] = fb.y;
            Bs[d4 * 4 + 2][row] = fb.z; Bs[d4 * 4 + 3][row] = fb.w;
        }
        __syncthreads();
#pragma unroll
        for (int dd = 0; dd < 16; dd++) {
            float a[8];
            *(float4*)&a[0] = *(float4*)&As[dd][ty * 4];
            *(float4*)&a[4] = *(float4*)&As[dd][64 + ty * 4];
            ulonglong2 b0 = *(ulonglong2*)&Bs[dd][tx * 4];
            ulonglong2 b1 = *(ulonglong2*)&Bs[dd][64 + tx * 4];
            unsigned long long bp[4] = {b0.x, b0.y, b1.x, b1.y};
            unsigned long long ad[8];
#pragma unroll
            for (int i = 0; i < 8; i++) ad[i] = pack2(a[i]);
#pragma unroll
            for (int i = 0; i < 8; i++)
#pragma unroll
                for (int j = 0; j < 4; j++) ffma2(acc[i][j], ad[i], bp[j]);
        }
        __syncthreads();
    }

    float* ab = attn + (size_t)hb * LL * LL;
    const int* mb = mask + (size_t)b * LL * LL;
#pragma unroll
    for (int i = 0; i < 8; i++) {
        int r = q0 + ((i < 4) ? ty * 4 + i : 64 + ty * 4 + (i - 4));
        float rowsum = 0.0f;
#pragma unroll
        for (int jj = 0; jj < 2; jj++) {
            int cb = k0 + (jj ? 64 + tx * 4 : tx * 4);
            int4 mv = *(const int4*)(mb + (size_t)r * LL + cb);
            float2 u0 = unpk(acc[i][jj * 2 + 0]);
            float2 u1 = unpk(acc[i][jj * 2 + 1]);
            float4 e;
            e.x = mv.x ? __expf(u0.x) : 0.0f;
            e.y = mv.y ? __expf(u0.y) : 0.0f;
            e.z = mv.z ? __expf(u1.x) : 0.0f;
            e.w = mv.w ? __expf(u1.y) : 0.0f;
            *(float4*)(ab + (size_t)r * LL + cb) = e;
            rowsum += e.x + e.y + e.z + e.w;
        }
#pragma unroll
        for (int o = 1; o < 16; o <<= 1)
            rowsum += __shfl_xor_sync(0xffffffffu, rowsum, o);
        if (tx == 0)
            g_psum[(size_t)(hb * LL + r) * KT + kt] = rowsum;
    }
}

// =====================================================================
// Kernel 2b: combine tile sums -> 1/rowsum
// =====================================================================
__global__ __launch_bounds__(256) void combine_kernel()
{
    int r = blockIdx.x * 256 + threadIdx.x;   // 32768 rows
    float L = 0.0f;
#pragma unroll
    for (int j = 0; j < KT; j++) L += g_psum[(size_t)r * KT + j];
    g_linv[r] = 1.0f / L;
}

// =====================================================================
// Kernel 2c: P = E * linv (written back) and ctx_part = P@V over k-split.
// 128q x 64d tile, 256 threads, 8x4 microtile (row-pair packed A).
// =====================================================================
__global__ __launch_bounds__(256) void pv_kernel(float* __restrict__ attn)
{
    __shared__ float Ps[32][132];   // [k][q], +4 pad
    __shared__ float Vs[32][68];    // [k][d], +4 pad

    const int hb = blockIdx.y;
    const int q0 = blockIdx.x * 128;
    const int ks = blockIdx.z;
    const int t = threadIdx.x, tx = t & 15, ty = t >> 4;   // tx: 4 cols, ty: 8 rows

    float* attnBase = attn + (size_t)hb * LL * LL + (size_t)q0 * LL;
    const float* vhBase = g_vh + (size_t)hb * LL * DKK;
    float* ctxp = ks ? g_ctxb : g_ctxa;

    // transform-phase row scales: rows (t>>3) + p*32
    float lrow[4];
#pragma unroll
    for (int p = 0; p < 4; p++)
        lrow[p] = g_linv[hb * LL + q0 + (t >> 3) + p * 32];

    unsigned long long acc[4][4];   // [row-pair][col]
#pragma unroll
    for (int i = 0; i < 4; i++)
#pragma unroll
        for (int j = 0; j < 4; j++) acc[i][j] = 0ull;

    const int kbeg = ks * (LL / 2);
    const int kend = kbeg + (LL / 2);
    for (int k0 = kbeg; k0 < kend; k0 += 32) {
        // stage 128x32 E tile -> P (write back) -> Ps transposed
#pragma unroll
        for (int p = 0; p < 4; p++) {
            int fi = t + p * 256;
            int col4 = fi & 7, row = fi >> 3;
            float* gp = attnBase + (size_t)row * LL + k0 + col4 * 4;
            float4 ev = *(const float4*)gp;
            float li = lrow[p];
            float4 pvv = {ev.x * li, ev.y * li, ev.z * li, ev.w * li};
            *(float4*)gp = pvv;
            int c = col4 * 4;
            Ps[c + 0][row] = pvv.x; Ps[c + 1][row] = pvv.y;
            Ps[c + 2][row] = pvv.z; Ps[c + 3][row] = pvv.w;
        }
        // stage V 32x64
#pragma unroll
        for (int p = 0; p < 2; p++) {
            int fi = t + p * 256;
            int d4 = fi & 15, kr = fi >> 4;
            float4 f = *(const float4*)(vhBase + (size_t)(k0 + kr) * DKK + d4 * 4);
            *(float4*)&Vs[kr][d4 * 4] = f;
        }
        __syncthreads();
#pragma unroll
        for (int kk = 0; kk < 32; kk++) {
            // A: 8 rows as 4 natural packed pairs (addr depends only on ty -> broadcast)
            ulonglong2 A0 = *(ulonglong2*)&Ps[kk][ty * 8];
            ulonglong2 A1 = *(ulonglong2*)&Ps[kk][ty * 8 + 4];
            unsigned long long ap[4] = {A0.x, A0.y, A1.x, A1.y};
            // B: 4 cols (addr depends only on tx)
            float4 bv = *(float4*)&Vs[kk][tx * 4];
            unsigned long long bp[4] = {pack2(bv.x), pack2(bv.y), pack2(bv.z), pack2(bv.w)};
#pragma unroll
            for (int i = 0; i < 4; i++)
#pragma unroll
                for (int j = 0; j < 4; j++) ffma2(acc[i][j], ap[i], bp[j]);
        }
        __syncthreads();
    }

    // ctx: rows q0 + ty*8 + 2i(+1), cols h*64 + tx*4
    const int h = hb >> 1, b = hb & 1;
#pragma unroll
    for (int i = 0; i < 4; i++) {
        float lo[4], hi[4];
#pragma unroll
        for (int j = 0; j < 4; j++) {
            float2 u = unpk(acc[i][j]);
            lo[j] = u.x; hi[j] = u.y;
        }
        int row = q0 + ty * 8 + 2 * i;
        float* o0 = ctxp + (size_t)(b * LL + row) * DMODEL + h * 64 + tx * 4;
        *(float4*)o0            = *(float4*)&lo[0];
        *(float4*)(o0 + DMODEL) = *(float4*)&hi[0];
    }
}

// =====================================================================
// Kernel 3: out = (ctxa + ctxb) @ Wo + bo + residual(q)
// =====================================================================
__global__ __launch_bounds__(256) void outproj_kernel(
    const float* __restrict__ resid, const float* __restrict__ Wo,
    const float* __restrict__ bo, float* __restrict__ out)
{
    __shared__ float As[16][128];
    __shared__ float Bs[16][128];

    const int col0 = blockIdx.x * 128;
    const int row0 = blockIdx.y * 128;
    const int t = threadIdx.x, tx = t & 15, ty = t >> 4;

    unsigned long long acc[8][4];
#pragma unroll
    for (int i = 0; i < 8; i++)
#pragma unroll
        for (int j = 0; j < 4; j++) acc[i][j] = 0ull;

    for (int k0 = 0; k0 < DMODEL; k0 += 16) {
#pragma unroll
        for (int p = 0; p < 2; p++) {
            int fi = t + p * 256;
            int k4 = fi & 3, row = fi >> 2;
            size_t ia = (size_t)(row0 + row) * DMODEL + k0 + k4 * 4;
            float4 fa = *(const float4*)(g_ctxa + ia);
            float4 f2 = *(const float4*)(g_ctxb + ia);
            As[k4 * 4 + 0][row] = fa.x + f2.x; As[k4 * 4 + 1][row] = fa.y + f2.y;
            As[k4 * 4 + 2][row] = fa.z + f2.z; As[k4 * 4 + 3][row] = fa.w + f2.w;
            int c4 = fi & 31, kk = fi >> 5;
            float4 fb = *(const float4*)(Wo + (size_t)(k0 + kk) * DMODEL + col0 + c4 * 4);
            *(float4*)&Bs[kk][c4 * 4] = fb;
        }
        __syncthreads();
#pragma unroll
        for (int kk = 0; kk < 16; kk++) {
            float a[8];
            *(float4*)&a[0] = *(float4*)&As[kk][ty * 4];
            *(float4*)&a[4] = *(float4*)&As[kk][64 + ty * 4];
            ulonglong2 b0 = *(ulonglong2*)&Bs[kk][tx * 4];
            ulonglong2 b1 = *(ulonglong2*)&Bs[kk][64 + tx * 4];
            unsigned long long bp[4] = {b0.x, b0.y, b1.x, b1.y};
            unsigned long long ad[8];
#pragma unroll
            for (int i = 0; i < 8; i++) ad[i] = pack2(a[i]);
#pragma unroll
            for (int i = 0; i < 8; i++)
#pragma unroll
                for (int j = 0; j < 4; j++) ffma2(acc[i][j], ad[i], bp[j]);
        }
        __syncthreads();
    }

#pragma unroll
    for (int i = 0; i < 8; i++) {
        int row = row0 + ((i < 4) ? ty * 4 + i : 64 + ty * 4 + (i - 4));
#pragma unroll
        for (int jj = 0; jj < 2; jj++) {
            int cb = col0 + (jj ? 64 + tx * 4 : tx * 4);
            float4 rb = *(const float4*)(resid + (size_t)row * DMODEL + cb);
            float4 bb = *(const float4*)(bo + cb);
            float2 u0 = unpk(acc[i][jj * 2 + 0]);
            float2 u1 = unpk(acc[i][jj * 2 + 1]);
            float4 o;
            o.x = u0.x + bb.x + rb.x;
            o.y = u0.y + bb.y + rb.y;
            o.z = u1.x + bb.z + rb.z;
            o.w = u1.y + bb.w + rb.w;
            *(float4*)(out + (size_t)row * DMODEL + cb) = o;
        }
    }
}

// =====================================================================
extern "C" void kernel_launch(void* const* d_in, const int* in_sizes, int n_in,
                              void* d_out, int out_size)
{
    const float* q    = (const float*)d_in[0];
    const float* k    = (const float*)d_in[1];
    const float* v    = (const float*)d_in[2];
    const int*   mask = (const int*)  d_in[3];
    const float* Wq   = (const float*)d_in[4];
    const float* bq   = (const float*)d_in[5];
    const float* Wk   = (const float*)d_in[6];
    const float* bk   = (const float*)d_in[7];
    const float* Wv   = (const float*)d_in[8];
    const float* bv   = (const float*)d_in[9];
    const float* Wo   = (const float*)d_in[10];
    const float* bo   = (const float*)d_in[11];

    float* out  = (float*)d_out;
    float* attn = out + (size_t)NT * DMODEL;

    proj_kernel<<<dim3(4, 32, 3), 256>>>(q, k, v, Wq, bq, Wk, bk, Wv, bv);
    scores_kernel<<<dim3(16, 16, 16), 256>>>(mask, attn);
    combine_kernel<<<128, 256>>>();
    pv_kernel<<<dim3(16, 16, 2), 256>>>(attn);
    outproj_kernel<<<dim3(4, 32), 256>>>(q, Wo, bo, out);
}

// round 7
// speedup vs baseline: 1.6084x; 1.2896x over previous
#include <cuda_runtime.h>
#include <cuda_bf16.h>
#include <cstdint>

#define LL   2048
#define BB   2
#define DMODEL 512
#define HH   8
#define DKK  64
#define NT   4096   // BB*LL
#define HB   16     // HH*BB
#define KT2  32     // psum slots per row (16 ktiles x 2 warp k-groups)

// ---------------- scratch (device globals; no allocation allowed) ----------------
__device__ __nv_bfloat16 g_qhb[HB * LL * DKK];  // [hb][l][d] bf16, pre-scaled 1/64
__device__ __nv_bfloat16 g_khb[HB * LL * DKK];
__device__ __nv_bfloat16 g_vhb[HB * LL * DKK];
__device__ float g_ctxa[NT * DMODEL];   // ctx partial, k-split 0
__device__ float g_ctxb[NT * DMODEL];   // ctx partial, k-split 1
__device__ float g_psum[HB * LL * KT2]; // per (row, ktile, kwarp) sum of exp(S)
__device__ float g_linv[HB * LL];       // 1 / row sumexp

// ---------------- packed f32x2 helpers (FFMA2) ----------------
__device__ __forceinline__ unsigned long long pack2(float x) {
    unsigned long long r;
    asm("mov.b64 %0, {%1, %1};" : "=l"(r) : "f"(x));
    return r;
}
__device__ __forceinline__ void ffma2(unsigned long long& d, unsigned long long a, unsigned long long b) {
    asm("fma.rn.f32x2 %0, %1, %2, %0;" : "+l"(d) : "l"(a), "l"(b));
}
__device__ __forceinline__ float2 unpk(unsigned long long p) {
    float2 r;
    asm("mov.b64 {%0, %1}, %2;" : "=f"(r.x), "=f"(r.y) : "l"(p));
    return r;
}

// ---------------- warp mma helpers ----------------
__device__ __forceinline__ uint32_t smem_u32(const void* p) {
    uint32_t a;
    asm("{ .reg .u64 t; cvta.to.shared.u64 t, %1; cvt.u32.u64 %0, t; }" : "=r"(a) : "l"(p));
    return a;
}
__device__ __forceinline__ uint32_t bf16x2(float lo, float hi) {
    uint32_t r;
    asm("cvt.rn.bf16x2.f32 %0, %1, %2;" : "=r"(r) : "f"(hi), "f"(lo));
    return r;
}
__device__ __forceinline__ void ldsm4(uint32_t* r, uint32_t addr) {
    asm volatile("ldmatrix.sync.aligned.m8n8.x4.shared.b16 {%0,%1,%2,%3}, [%4];"
                 : "=r"(r[0]), "=r"(r[1]), "=r"(r[2]), "=r"(r[3]) : "r"(addr));
}
__device__ __forceinline__ void ldsm4t(uint32_t* r, uint32_t addr) {
    asm volatile("ldmatrix.sync.aligned.m8n8.x4.trans.shared.b16 {%0,%1,%2,%3}, [%4];"
                 : "=r"(r[0]), "=r"(r[1]), "=r"(r[2]), "=r"(r[3]) : "r"(addr));
}
__device__ __forceinline__ void mma_bf16(float* c, const uint32_t* a, uint32_t b0, uint32_t b1) {
    asm volatile(
        "mma.sync.aligned.m16n8k16.row.col.f32.bf16.bf16.f32 "
        "{%0,%1,%2,%3}, {%4,%5,%6,%7}, {%8,%9}, {%0,%1,%2,%3};"
        : "+f"(c[0]), "+f"(c[1]), "+f"(c[2]), "+f"(c[3])
        : "r"(a[0]), "r"(a[1]), "r"(a[2]), "r"(a[3]), "r"(b0), "r"(b1));
}

// =====================================================================
// Kernel 1: fused QKV projection.  Yb = bf16((X @ W + b) [* 1/64 for Q])
// =====================================================================
__global__ __launch_bounds__(256) void proj_kernel(
    const float* __restrict__ qin, const float* __restrict__ kin, const float* __restrict__ vin,
    const float* __restrict__ Wq, const float* __restrict__ bq,
    const float* __restrict__ Wk, const float* __restrict__ bk,
    const float* __restrict__ Wv, const float* __restrict__ bv)
{
    __shared__ float As[16][128];   // [k][row]
    __shared__ float Bs[16][128];   // [k][col]

    const int z = blockIdx.z;
    const float* X    = (z == 0) ? qin : (z == 1) ? kin : vin;
    const float* W    = (z == 0) ? Wq  : (z == 1) ? Wk  : Wv;
    const float* bias = (z == 0) ? bq  : (z == 1) ? bk  : bv;
    __nv_bfloat16* outp = (z == 0) ? g_qhb : (z == 1) ? g_khb : g_vhb;
    const float scale = (z == 0) ? (1.0f / 64.0f) : 1.0f;

    const int col0 = blockIdx.x * 128;
    const int row0 = blockIdx.y * 128;
    const int t = threadIdx.x, tx = t & 15, ty = t >> 4;

    unsigned long long acc[8][4];
#pragma unroll
    for (int i = 0; i < 8; i++)
#pragma unroll
        for (int j = 0; j < 4; j++) acc[i][j] = 0ull;

    for (int k0 = 0; k0 < DMODEL; k0 += 16) {
#pragma unroll
        for (int p = 0; p < 2; p++) {
            int fi = t + p * 256;
            int k4 = fi & 3, row = fi >> 2;
            float4 fa = *(const float4*)(X + (size_t)(row0 + row) * DMODEL + k0 + k4 * 4);
            As[k4 * 4 + 0][row] = fa.x; As[k4 * 4 + 1][row] = fa.y;
            As[k4 * 4 + 2][row] = fa.z; As[k4 * 4 + 3][row] = fa.w;
            int c4 = fi & 31, kk = fi >> 5;
            float4 fb = *(const float4*)(W + (size_t)(k0 + kk) * DMODEL + col0 + c4 * 4);
            *(float4*)&Bs[kk][c4 * 4] = fb;
        }
        __syncthreads();
#pragma unroll
        for (int kk = 0; kk < 16; kk++) {
            float a[8];
            *(float4*)&a[0] = *(float4*)&As[kk][ty * 4];
            *(float4*)&a[4] = *(float4*)&As[kk][64 + ty * 4];
            ulonglong2 b0 = *(ulonglong2*)&Bs[kk][tx * 4];
            ulonglong2 b1 = *(ulonglong2*)&Bs[kk][64 + tx * 4];
            unsigned long long bp[4] = {b0.x, b0.y, b1.x, b1.y};
            unsigned long long ad[8];
#pragma unroll
            for (int i = 0; i < 8; i++) ad[i] = pack2(a[i]);
#pragma unroll
            for (int i = 0; i < 8; i++)
#pragma unroll
                for (int j = 0; j < 4; j++) ffma2(acc[i][j], ad[i], bp[j]);
        }
        __syncthreads();
    }

#pragma unroll
    for (int i = 0; i < 8; i++) {
        int row = row0 + ((i < 4) ? ty * 4 + i : 64 + ty * 4 + (i - 4));
        int bidx = row >> 11, l = row & 2047;
#pragma unroll
        for (int jj = 0; jj < 2; jj++) {
            int colb = col0 + (jj ? 64 + tx * 4 : tx * 4);
            int h = colb >> 6, d = colb & 63;
            float2 u0 = unpk(acc[i][jj * 2 + 0]);
            float2 u1 = unpk(acc[i][jj * 2 + 1]);
            float ox = (u0.x + bias[colb + 0]) * scale;
            float oy = (u0.y + bias[colb + 1]) * scale;
            float oz = (u1.x + bias[colb + 2]) * scale;
            float ow = (u1.y + bias[colb + 3]) * scale;
            uint2 pk = {bf16x2(ox, oy), bf16x2(oz, ow)};
            *(uint2*)(outp + (size_t)((h * BB + bidx) * LL + l) * DKK + d) = pk;
        }
    }
}

// =====================================================================
// Kernel 2a: E = exp((Q/64) @ K^T) masked->0 via bf16 mma.sync.
// CTA: 128q x 128k per (hb, qt, kt). 8 warps, warp tile 32q x 64k.
// =====================================================================
__global__ __launch_bounds__(256) void scores_kernel(
    const int* __restrict__ mask, float* __restrict__ attn)
{
    __shared__ __nv_bfloat16 Qs[128][72];
    __shared__ __nv_bfloat16 Ks[128][72];

    const int hb = blockIdx.z;
    const int q0 = blockIdx.y * 128;
    const int k0 = blockIdx.x * 128;
    const int kt = blockIdx.x;
    const int bat = hb & 1;
    const int t = threadIdx.x, w = t >> 5, l = t & 31;

    const __nv_bfloat16* qb = g_qhb + (size_t)hb * LL * DKK + (size_t)q0 * DKK;
    const __nv_bfloat16* kb = g_khb + (size_t)hb * LL * DKK + (size_t)k0 * DKK;

#pragma unroll
    for (int p = 0; p < 4; p++) {
        int fi = t + p * 256;
        int row = fi >> 3, c8 = fi & 7;
        *(uint4*)&Qs[row][c8 * 8] = *(const uint4*)(qb + (size_t)row * DKK + c8 * 8);
        *(uint4*)&Ks[row][c8 * 8] = *(const uint4*)(kb + (size_t)row * DKK + c8 * 8);
    }
    __syncthreads();

    const int qw = (w >> 1) * 32;     // warp q offset in tile
    const int kw = (w & 1) * 64;      // warp k offset in tile

    float acc[2][8][4];
#pragma unroll
    for (int mt = 0; mt < 2; mt++)
#pragma unroll
        for (int nt = 0; nt < 8; nt++)
#pragma unroll
            for (int e = 0; e < 4; e++) acc[mt][nt][e] = 0.0f;

#pragma unroll
    for (int d0 = 0; d0 < 64; d0 += 16) {
        uint32_t a[2][4];
#pragma unroll
        for (int mt = 0; mt < 2; mt++)
            ldsm4(a[mt], smem_u32(&Qs[qw + mt * 16 + (l & 15)][d0 + (l >> 4) * 8]));
#pragma unroll
        for (int ntp = 0; ntp < 4; ntp++) {
            uint32_t bfr[4];
            int nrow = kw + ntp * 16 + (l & 7) + 8 * (l >> 4);
            ldsm4(bfr, smem_u32(&Ks[nrow][d0 + 8 * ((l >> 3) & 1)]));
#pragma unroll
            for (int mt = 0; mt < 2; mt++) {
                mma_bf16(acc[mt][ntp * 2 + 0], a[mt], bfr[0], bfr[1]);
                mma_bf16(acc[mt][ntp * 2 + 1], a[mt], bfr[2], bfr[3]);
            }
        }
    }

    // epilogue: mask -> exp -> store E, quad rowsum -> g_psum
    float* ab = attn + (size_t)hb * LL * LL;
    const int* mb = mask + (size_t)bat * LL * LL;
#pragma unroll
    for (int mt = 0; mt < 2; mt++) {
        int r0 = q0 + qw + mt * 16 + (l >> 2);
        int r1 = r0 + 8;
        float s0 = 0.0f, s1 = 0.0f;
#pragma unroll
        for (int nt = 0; nt < 8; nt++) {
            int c = k0 + kw + nt * 8 + (l & 3) * 2;
            int2 m0 = *(const int2*)(mb + (size_t)r0 * LL + c);
            int2 m1 = *(const int2*)(mb + (size_t)r1 * LL + c);
            float e00 = m0.x ? __expf(acc[mt][nt][0]) : 0.0f;
            float e01 = m0.y ? __expf(acc[mt][nt][1]) : 0.0f;
            float e10 = m1.x ? __expf(acc[mt][nt][2]) : 0.0f;
            float e11 = m1.y ? __expf(acc[mt][nt][3]) : 0.0f;
            float2 w0 = {e00, e01}, w1 = {e10, e11};
            *(float2*)(ab + (size_t)r0 * LL + c) = w0;
            *(float2*)(ab + (size_t)r1 * LL + c) = w1;
            s0 += e00 + e01;
            s1 += e10 + e11;
        }
        s0 += __shfl_xor_sync(0xffffffffu, s0, 1);
        s0 += __shfl_xor_sync(0xffffffffu, s0, 2);
        s1 += __shfl_xor_sync(0xffffffffu, s1, 1);
        s1 += __shfl_xor_sync(0xffffffffu, s1, 2);
        if ((l & 3) == 0) {
            g_psum[(size_t)(hb * LL + r0) * KT2 + kt * 2 + (w & 1)] = s0;
            g_psum[(size_t)(hb * LL + r1) * KT2 + kt * 2 + (w & 1)] = s1;
        }
    }
}

// =====================================================================
// Kernel 2b: combine tile sums -> 1/rowsum
// =====================================================================
__global__ __launch_bounds__(256) void combine_kernel()
{
    int r = blockIdx.x * 256 + threadIdx.x;   // 32768 rows
    float L = 0.0f;
#pragma unroll
    for (int j = 0; j < KT2; j++) L += g_psum[(size_t)r * KT2 + j];
    g_linv[r] = 1.0f / L;
}

// =====================================================================
// Kernel 2c: P = E * linv (fp32 writeback) and ctx_part = P@V (bf16 mma).
// CTA: 128q x 64d, k chunk 64, 16 stages per k-split. 8 warps, 32q x 32d.
// =====================================================================
__global__ __launch_bounds__(256) void pv_kernel(float* __restrict__ attn)
{
    __shared__ __nv_bfloat16 Ps[128][72];
    __shared__ __nv_bfloat16 Vs[64][72];

    const int hb = blockIdx.y;
    const int q0 = blockIdx.x * 128;
    const int ks = blockIdx.z;
    const int t = threadIdx.x, w = t >> 5, l = t & 31;

    float* attnBase = attn + (size_t)hb * LL * LL + (size_t)q0 * LL;
    const __nv_bfloat16* vb = g_vhb + (size_t)hb * LL * DKK;
    float* ctxp = ks ? g_ctxb : g_ctxa;

    float lrow[8];
#pragma unroll
    for (int p = 0; p < 8; p++)
        lrow[p] = g_linv[hb * LL + q0 + (t >> 4) + p * 16];

    const int qw = (w >> 1) * 32;
    const int dw = (w & 1) * 32;

    float acc[2][4][4];
#pragma unroll
    for (int mt = 0; mt < 2; mt++)
#pragma unroll
        for (int nt = 0; nt < 4; nt++)
#pragma unroll
            for (int e = 0; e < 4; e++) acc[mt][nt][e] = 0.0f;

    for (int s = 0; s < 16; s++) {
        const int k0 = ks * 1024 + s * 64;
        // E -> P (writeback fp32) -> Ps bf16
#pragma unroll
        for (int p = 0; p < 8; p++) {
            int fi = t + p * 256;
            int row = fi >> 4, c4 = fi & 15;
            float* gp = attnBase + (size_t)row * LL + k0 + c4 * 4;
            float4 e = *(const float4*)gp;
            float li = lrow[p];
            float4 pv = {e.x * li, e.y * li, e.z * li, e.w * li};
            *(float4*)gp = pv;
            uint2 pk = {bf16x2(pv.x, pv.y), bf16x2(pv.z, pv.w)};
            *(uint2*)&Ps[row][c4 * 4] = pk;
        }
        // V chunk 64 x 64 bf16
#pragma unroll
        for (int p = 0; p < 2; p++) {
            int fi = t + p * 256;
            int row = fi >> 3, c8 = fi & 7;
            *(uint4*)&Vs[row][c8 * 8] = *(const uint4*)(vb + (size_t)(k0 + row) * DKK + c8 * 8);
        }
        __syncthreads();
#pragma unroll
        for (int kk0 = 0; kk0 < 64; kk0 += 16) {
            uint32_t a[2][4];
#pragma unroll
            for (int mt = 0; mt < 2; mt++)
                ldsm4(a[mt], smem_u32(&Ps[qw + mt * 16 + (l & 15)][kk0 + (l >> 4) * 8]));
#pragma unroll
            for (int ntp = 0; ntp < 2; ntp++) {
                uint32_t bfr[4];
                int krow = kk0 + (l & 7) + 8 * ((l >> 3) & 1);
                ldsm4t(bfr, smem_u32(&Vs[krow][dw + ntp * 16 + 8 * (l >> 4)]));
#pragma unroll
                for (int mt = 0; mt < 2; mt++) {
                    mma_bf16(acc[mt][ntp * 2 + 0], a[mt], bfr[0], bfr[1]);
                    mma_bf16(acc[mt][ntp * 2 + 1], a[mt], bfr[2], bfr[3]);
                }
            }
        }
        __syncthreads();
    }

    // epilogue: ctx partial [b*L + l][h*64 + d]
    const int h = hb >> 1, bat = hb & 1;
#pragma unroll
    for (int mt = 0; mt < 2; mt++) {
        int r0 = q0 + qw + mt * 16 + (l >> 2);
        int r1 = r0 + 8;
#pragma unroll
        for (int nt = 0; nt < 4; nt++) {
            int c = dw + nt * 8 + (l & 3) * 2;
            float2 w0 = {acc[mt][nt][0], acc[mt][nt][1]};
            float2 w1 = {acc[mt][nt][2], acc[mt][nt][3]};
            *(float2*)(ctxp + (size_t)(bat * LL + r0) * DMODEL + h * 64 + c) = w0;
            *(float2*)(ctxp + (size_t)(bat * LL + r1) * DMODEL + h * 64 + c) = w1;
        }
    }
}

// =====================================================================
// Kernel 3: out = (ctxa + ctxb) @ Wo + bo + residual(q)
// =====================================================================
__global__ __launch_bounds__(256) void outproj_kernel(
    const float* __restrict__ resid, const float* __restrict__ Wo,
    const float* __restrict__ bo, float* __restrict__ out)
{
    __shared__ float As[16][128];
    __shared__ float Bs[16][128];

    const int col0 = blockIdx.x * 128;
    const int row0 = blockIdx.y * 128;
    const int t = threadIdx.x, tx = t & 15, ty = t >> 4;

    unsigned long long acc[8][4];
#pragma unroll
    for (int i = 0; i < 8; i++)
#pragma unroll
        for (int j = 0; j < 4; j++) acc[i][j] = 0ull;

    for (int k0 = 0; k0 < DMODEL; k0 += 16) {
#pragma unroll
        for (int p = 0; p < 2; p++) {
            int fi = t + p * 256;
            int k4 = fi & 3, row = fi >> 2;
            size_t ia = (size_t)(row0 + row) * DMODEL + k0 + k4 * 4;
            float4 fa = *(const float4*)(g_ctxa + ia);
            float4 f2 = *(const float4*)(g_ctxb + ia);
            As[k4 * 4 + 0][row] = fa.x + f2.x; As[k4 * 4 + 1][row] = fa.y + f2.y;
            As[k4 * 4 + 2][row] = fa.z + f2.z; As[k4 * 4 + 3][row] = fa.w + f2.w;
            int c4 = fi & 31, kk = fi >> 5;
            float4 fb = *(const float4*)(Wo + (size_t)(k0 + kk) * DMODEL + col0 + c4 * 4);
            *(float4*)&Bs[kk][c4 * 4] = fb;
        }
        __syncthreads();
#pragma unroll
        for (int kk = 0; kk < 16; kk++) {
            float a[8];
            *(float4*)&a[0] = *(float4*)&As[kk][ty * 4];
            *(float4*)&a[4] = *(float4*)&As[kk][64 + ty * 4];
            ulonglong2 b0 = *(ulonglong2*)&Bs[kk][tx * 4];
            ulonglong2 b1 = *(ulonglong2*)&Bs[kk][64 + tx * 4];
            unsigned long long bp[4] = {b0.x, b0.y, b1.x, b1.y};
            unsigned long long ad[8];
#pragma unroll
            for (int i = 0; i < 8; i++) ad[i] = pack2(a[i]);
#pragma unroll
            for (int i = 0; i < 8; i++)
#pragma unroll
                for (int j = 0; j < 4; j++) ffma2(acc[i][j], ad[i], bp[j]);
        }
        __syncthreads();
    }

#pragma unroll
    for (int i = 0; i < 8; i++) {
        int row = row0 + ((i < 4) ? ty * 4 + i : 64 + ty * 4 + (i - 4));
#pragma unroll
        for (int jj = 0; jj < 2; jj++) {
            int cb = col0 + (jj ? 64 + tx * 4 : tx * 4);
            float4 rb = *(const float4*)(resid + (size_t)row * DMODEL + cb);
            float4 bb = *(const float4*)(bo + cb);
            float2 u0 = unpk(acc[i][jj * 2 + 0]);
            float2 u1 = unpk(acc[i][jj * 2 + 1]);
            float4 o;
            o.x = u0.x + bb.x + rb.x;
            o.y = u0.y + bb.y + rb.y;
            o.z = u1.x + bb.z + rb.z;
            o.w = u1.y + bb.w + rb.w;
            *(float4*)(out + (size_t)row * DMODEL + cb) = o;
        }
    }
}

// =====================================================================
extern "C" void kernel_launch(void* const* d_in, const int* in_sizes, int n_in,
                              void* d_out, int out_size)
{
    const float* q    = (const float*)d_in[0];
    const float* k    = (const float*)d_in[1];
    const float* v    = (const float*)d_in[2];
    const int*   mask = (const int*)  d_in[3];
    const float* Wq   = (const float*)d_in[4];
    const float* bq   = (const float*)d_in[5];
    const float* Wk   = (const float*)d_in[6];
    const float* bk   = (const float*)d_in[7];
    const float* Wv   = (const float*)d_in[8];
    const float* bv   = (const float*)d_in[9];
    const float* Wo   = (const float*)d_in[10];
    const float* bo   = (const float*)d_in[11];

    float* out  = (float*)d_out;
    float* attn = out + (size_t)NT * DMODEL;

    proj_kernel<<<dim3(4, 32, 3), 256>>>(q, k, v, Wq, bq, Wk, bk, Wv, bv);
    scores_kernel<<<dim3(16, 16, 16), 256>>>(mask, attn);
    combine_kernel<<<128, 256>>>();
    pv_kernel<<<dim3(16, 16, 2), 256>>>(attn);
    outproj_kernel<<<dim3(4, 32), 256>>>(q, Wo, bo, out);
}

// round 8
// speedup vs baseline: 1.7339x; 1.0780x over previous
#include <cuda_runtime.h>
#include <cuda_bf16.h>
#include <cstdint>

#define LL   2048
#define BB   2
#define DMODEL 512
#define HH   8
#define DKK  64
#define NT   4096   // BB*LL
#define HB   16     // HH*BB

// ---------------- scratch (device globals; no allocation allowed) ----------------
__device__ __nv_bfloat16 g_qhb[HB * LL * DKK];  // [hb][l][d] bf16, pre-scaled 1/64
__device__ __nv_bfloat16 g_khb[HB * LL * DKK];
__device__ __nv_bfloat16 g_vhb[HB * LL * DKK];
__device__ float g_ctx[NT * DMODEL];    // ctx [b*L+l][h*64+d]
__device__ float g_linv[HB * LL];       // 1 / row sumexp

// ---------------- packed f32x2 helpers (FFMA2) ----------------
__device__ __forceinline__ unsigned long long pack2(float x) {
    unsigned long long r;
    asm("mov.b64 %0, {%1, %1};" : "=l"(r) : "f"(x));
    return r;
}
__device__ __forceinline__ void ffma2(unsigned long long& d, unsigned long long a, unsigned long long b) {
    asm("fma.rn.f32x2 %0, %1, %2, %0;" : "+l"(d) : "l"(a), "l"(b));
}
__device__ __forceinline__ float2 unpk(unsigned long long p) {
    float2 r;
    asm("mov.b64 {%0, %1}, %2;" : "=f"(r.x), "=f"(r.y) : "l"(p));
    return r;
}

// ---------------- warp mma helpers ----------------
__device__ __forceinline__ uint32_t smem_u32(const void* p) {
    uint32_t a;
    asm("{ .reg .u64 t; cvta.to.shared.u64 t, %1; cvt.u32.u64 %0, t; }" : "=r"(a) : "l"(p));
    return a;
}
__device__ __forceinline__ uint32_t bf16x2(float lo, float hi) {
    uint32_t r;
    asm("cvt.rn.bf16x2.f32 %0, %1, %2;" : "=r"(r) : "f"(hi), "f"(lo));
    return r;
}
__device__ __forceinline__ void ldsm4(uint32_t* r, uint32_t addr) {
    asm volatile("ldmatrix.sync.aligned.m8n8.x4.shared.b16 {%0,%1,%2,%3}, [%4];"
                 : "=r"(r[0]), "=r"(r[1]), "=r"(r[2]), "=r"(r[3]) : "r"(addr));
}
__device__ __forceinline__ void ldsm4t(uint32_t* r, uint32_t addr) {
    asm volatile("ldmatrix.sync.aligned.m8n8.x4.trans.shared.b16 {%0,%1,%2,%3}, [%4];"
                 : "=r"(r[0]), "=r"(r[1]), "=r"(r[2]), "=r"(r[3]) : "r"(addr));
}
__device__ __forceinline__ void mma_bf16(float* c, const uint32_t* a, uint32_t b0, uint32_t b1) {
    asm volatile(
        "mma.sync.aligned.m16n8k16.row.col.f32.bf16.bf16.f32 "
        "{%0,%1,%2,%3}, {%4,%5,%6,%7}, {%8,%9}, {%0,%1,%2,%3};"
        : "+f"(c[0]), "+f"(c[1]), "+f"(c[2]), "+f"(c[3])
        : "r"(a[0]), "r"(a[1]), "r"(a[2]), "r"(a[3]), "r"(b0), "r"(b1));
}

// =====================================================================
// Kernel 1: fused QKV projection.  Yb = bf16((X @ W + b) [* 1/64 for Q])
// =====================================================================
__global__ __launch_bounds__(256) void proj_kernel(
    const float* __restrict__ qin, const float* __restrict__ kin, const float* __restrict__ vin,
    const float* __restrict__ Wq, const float* __restrict__ bq,
    const float* __restrict__ Wk, const float* __restrict__ bk,
    const float* __restrict__ Wv, const float* __restrict__ bv)
{
    __shared__ float As[16][128];   // [k][row]
    __shared__ float Bs[16][128];   // [k][col]

    const int z = blockIdx.z;
    const float* X    = (z == 0) ? qin : (z == 1) ? kin : vin;
    const float* W    = (z == 0) ? Wq  : (z == 1) ? Wk  : Wv;
    const float* bias = (z == 0) ? bq  : (z == 1) ? bk  : bv;
    __nv_bfloat16* outp = (z == 0) ? g_qhb : (z == 1) ? g_khb : g_vhb;
    const float scale = (z == 0) ? (1.0f / 64.0f) : 1.0f;

    const int col0 = blockIdx.x * 128;
    const int row0 = blockIdx.y * 128;
    const int t = threadIdx.x, tx = t & 15, ty = t >> 4;

    unsigned long long acc[8][4];
#pragma unroll
    for (int i = 0; i < 8; i++)
#pragma unroll
        for (int j = 0; j < 4; j++) acc[i][j] = 0ull;

    for (int k0 = 0; k0 < DMODEL; k0 += 16) {
#pragma unroll
        for (int p = 0; p < 2; p++) {
            int fi = t + p * 256;
            int k4 = fi & 3, row = fi >> 2;
            float4 fa = *(const float4*)(X + (size_t)(row0 + row) * DMODEL + k0 + k4 * 4);
            As[k4 * 4 + 0][row] = fa.x; As[k4 * 4 + 1][row] = fa.y;
            As[k4 * 4 + 2][row] = fa.z; As[k4 * 4 + 3][row] = fa.w;
            int c4 = fi & 31, kk = fi >> 5;
            float4 fb = *(const float4*)(W + (size_t)(k0 + kk) * DMODEL + col0 + c4 * 4);
            *(float4*)&Bs[kk][c4 * 4] = fb;
        }
        __syncthreads();
#pragma unroll
        for (int kk = 0; kk < 16; kk++) {
            float a[8];
            *(float4*)&a[0] = *(float4*)&As[kk][ty * 4];
            *(float4*)&a[4] = *(float4*)&As[kk][64 + ty * 4];
            ulonglong2 b0 = *(ulonglong2*)&Bs[kk][tx * 4];
            ulonglong2 b1 = *(ulonglong2*)&Bs[kk][64 + tx * 4];
            unsigned long long bp[4] = {b0.x, b0.y, b1.x, b1.y};
            unsigned long long ad[8];
#pragma unroll
            for (int i = 0; i < 8; i++) ad[i] = pack2(a[i]);
#pragma unroll
            for (int i = 0; i < 8; i++)
#pragma unroll
                for (int j = 0; j < 4; j++) ffma2(acc[i][j], ad[i], bp[j]);
        }
        __syncthreads();
    }

#pragma unroll
    for (int i = 0; i < 8; i++) {
        int row = row0 + ((i < 4) ? ty * 4 + i : 64 + ty * 4 + (i - 4));
        int bidx = row >> 11, l = row & 2047;
#pragma unroll
        for (int jj = 0; jj < 2; jj++) {
            int colb = col0 + (jj ? 64 + tx * 4 : tx * 4);
            int h = colb >> 6, d = colb & 63;
            float2 u0 = unpk(acc[i][jj * 2 + 0]);
            float2 u1 = unpk(acc[i][jj * 2 + 1]);
            float ox = (u0.x + bias[colb + 0]) * scale;
            float oy = (u0.y + bias[colb + 1]) * scale;
            float oz = (u1.x + bias[colb + 2]) * scale;
            float ow = (u1.y + bias[colb + 3]) * scale;
            uint2 pk = {bf16x2(ox, oy), bf16x2(oz, ow)};
            *(uint2*)(outp + (size_t)((h * BB + bidx) * LL + l) * DKK + d) = pk;
        }
    }
}

// =====================================================================
// Kernel 2: pass 1 — row sums of exp(S) in registers -> g_linv.
// CTA: 64 q rows, full k sweep (16 tiles of 128). 8 warps, 16q x 64k.
// =====================================================================
__global__ __launch_bounds__(256) void linv_kernel(const int* __restrict__ mask)
{
    __shared__ __nv_bfloat16 Qs[64][72];
    __shared__ __nv_bfloat16 Ks[128][72];
    __shared__ float sred[2][64];

    const int hb = blockIdx.y;
    const int q0 = blockIdx.x * 64;
    const int bat = hb & 1;
    const int t = threadIdx.x, w = t >> 5, l = t & 31;
    const int qw = (w >> 1) * 16;
    const int kwsel = w & 1;
    const int kw = kwsel * 64;

    const __nv_bfloat16* qb = g_qhb + (size_t)hb * LL * DKK + (size_t)q0 * DKK;
    const __nv_bfloat16* kb = g_khb + (size_t)hb * LL * DKK;
    const int* mb = mask + (size_t)bat * LL * LL;

#pragma unroll
    for (int p = 0; p < 2; p++) {
        int fi = t + p * 256;
        int row = fi >> 3, c8 = fi & 7;
        *(uint4*)&Qs[row][c8 * 8] = *(const uint4*)(qb + (size_t)row * DKK + c8 * 8);
    }

    float rs0 = 0.0f, rs1 = 0.0f;
    const int r0g = q0 + qw + (l >> 2);
    const int r1g = r0g + 8;

    for (int kt = 0; kt < 16; kt++) {
        const int k0 = kt * 128;
#pragma unroll
        for (int p = 0; p < 4; p++) {
            int fi = t + p * 256;
            int row = fi >> 3, c8 = fi & 7;
            *(uint4*)&Ks[row][c8 * 8] = *(const uint4*)(kb + (size_t)(k0 + row) * DKK + c8 * 8);
        }
        __syncthreads();

        float acc[8][4];
#pragma unroll
        for (int nt = 0; nt < 8; nt++)
#pragma unroll
            for (int e = 0; e < 4; e++) acc[nt][e] = 0.0f;

#pragma unroll
        for (int d0 = 0; d0 < 64; d0 += 16) {
            uint32_t a[4];
            ldsm4(a, smem_u32(&Qs[qw + (l & 15)][d0 + (l >> 4) * 8]));
#pragma unroll
            for (int ntp = 0; ntp < 4; ntp++) {
                uint32_t bfr[4];
                int nrow = kw + ntp * 16 + (l & 7) + 8 * (l >> 4);
                ldsm4(bfr, smem_u32(&Ks[nrow][d0 + 8 * ((l >> 3) & 1)]));
                mma_bf16(acc[ntp * 2 + 0], a, bfr[0], bfr[1]);
                mma_bf16(acc[ntp * 2 + 1], a, bfr[2], bfr[3]);
            }
        }

#pragma unroll
        for (int nt = 0; nt < 8; nt++) {
            int c = k0 + kw + nt * 8 + (l & 3) * 2;
            int2 m0 = *(const int2*)(mb + (size_t)r0g * LL + c);
            int2 m1 = *(const int2*)(mb + (size_t)r1g * LL + c);
            rs0 += (m0.x ? __expf(acc[nt][0]) : 0.0f) + (m0.y ? __expf(acc[nt][1]) : 0.0f);
            rs1 += (m1.x ? __expf(acc[nt][2]) : 0.0f) + (m1.y ? __expf(acc[nt][3]) : 0.0f);
        }
        __syncthreads();
    }

    rs0 += __shfl_xor_sync(0xffffffffu, rs0, 1);
    rs0 += __shfl_xor_sync(0xffffffffu, rs0, 2);
    rs1 += __shfl_xor_sync(0xffffffffu, rs1, 1);
    rs1 += __shfl_xor_sync(0xffffffffu, rs1, 2);
    if ((l & 3) == 0) {
        sred[kwsel][qw + (l >> 2)]     = rs0;
        sred[kwsel][qw + 8 + (l >> 2)] = rs1;
    }
    __syncthreads();
    if (t < 64)
        g_linv[hb * LL + q0 + t] = 1.0f / (sred[0][t] + sred[1][t]);
}

// =====================================================================
// Kernel 3: pass 2 — recompute S, P = mask*exp(S)*linv (write attn),
// accumulate ctx = P @ V in fp32 registers across full k.
// CTA: 64 q rows. 8 warps. S phase: 16q x 32k; PV phase: 16q x 32d.
// =====================================================================
__global__ __launch_bounds__(256) void pv2_kernel(const int* __restrict__ mask,
                                                  float* __restrict__ attn)
{
    __shared__ __nv_bfloat16 Qs[64][72];
    __shared__ __nv_bfloat16 Ks[64][72];
    __shared__ __nv_bfloat16 Vs[64][72];
    __shared__ __nv_bfloat16 Ps[64][72];

    const int hb = blockIdx.y;
    const int q0 = blockIdx.x * 64;
    const int bat = hb & 1;
    const int h = hb >> 1;
    const int t = threadIdx.x, w = t >> 5, l = t & 31;
    const int qw = (w >> 1) * 16;
    const int kw = (w & 1) * 32;   // S phase k offset within 64-chunk
    const int dw = (w & 1) * 32;   // PV phase d offset

    const __nv_bfloat16* qb = g_qhb + (size_t)hb * LL * DKK + (size_t)q0 * DKK;
    const __nv_bfloat16* kb = g_khb + (size_t)hb * LL * DKK;
    const __nv_bfloat16* vb = g_vhb + (size_t)hb * LL * DKK;
    const int* mb = mask + (size_t)bat * LL * LL;
    float* ab = attn + (size_t)hb * LL * LL;

#pragma unroll
    for (int p = 0; p < 2; p++) {
        int fi = t + p * 256;
        int row = fi >> 3, c8 = fi & 7;
        *(uint4*)&Qs[row][c8 * 8] = *(const uint4*)(qb + (size_t)row * DKK + c8 * 8);
    }

    const int r0g = q0 + qw + (l >> 2);
    const int r1g = r0g + 8;
    const float li0 = g_linv[hb * LL + r0g];
    const float li1 = g_linv[hb * LL + r1g];

    float acc_pv[4][4];
#pragma unroll
    for (int nt = 0; nt < 4; nt++)
#pragma unroll
        for (int e = 0; e < 4; e++) acc_pv[nt][e] = 0.0f;

    for (int s = 0; s < 32; s++) {
        const int k0 = s * 64;
#pragma unroll
        for (int p = 0; p < 2; p++) {
            int fi = t + p * 256;
            int row = fi >> 3, c8 = fi & 7;
            *(uint4*)&Ks[row][c8 * 8] = *(const uint4*)(kb + (size_t)(k0 + row) * DKK + c8 * 8);
            *(uint4*)&Vs[row][c8 * 8] = *(const uint4*)(vb + (size_t)(k0 + row) * DKK + c8 * 8);
        }
        __syncthreads();

        // S phase: warp computes 16q x 32k
        float acc_s[4][4];
#pragma unroll
        for (int nt = 0; nt < 4; nt++)
#pragma unroll
            for (int e = 0; e < 4; e++) acc_s[nt][e] = 0.0f;

#pragma unroll
        for (int d0 = 0; d0 < 64; d0 += 16) {
            uint32_t a[4];
            ldsm4(a, smem_u32(&Qs[qw + (l & 15)][d0 + (l >> 4) * 8]));
#pragma unroll
            for (int ntp = 0; ntp < 2; ntp++) {
                uint32_t bfr[4];
                int nrow = kw + ntp * 16 + (l & 7) + 8 * (l >> 4);
                ldsm4(bfr, smem_u32(&Ks[nrow][d0 + 8 * ((l >> 3) & 1)]));
                mma_bf16(acc_s[ntp * 2 + 0], a, bfr[0], bfr[1]);
                mma_bf16(acc_s[ntp * 2 + 1], a, bfr[2], bfr[3]);
            }
        }

        // epilogue: P = mask * exp(S) * linv; write attn; stage Ps bf16
#pragma unroll
        for (int nt = 0; nt < 4; nt++) {
            int cl = kw + nt * 8 + (l & 3) * 2;   // col within 64-chunk
            int c = k0 + cl;
            int2 m0 = *(const int2*)(mb + (size_t)r0g * LL + c);
            int2 m1 = *(const int2*)(mb + (size_t)r1g * LL + c);
            float p00 = m0.x ? __expf(acc_s[nt][0]) * li0 : 0.0f;
            float p01 = m0.y ? __expf(acc_s[nt][1]) * li0 : 0.0f;
            float p10 = m1.x ? __expf(acc_s[nt][2]) * li1 : 0.0f;
            float p11 = m1.y ? __expf(acc_s[nt][3]) * li1 : 0.0f;
            float2 w0 = {p00, p01}, w1 = {p10, p11};
            *(float2*)(ab + (size_t)r0g * LL + c) = w0;
            *(float2*)(ab + (size_t)r1g * LL + c) = w1;
            *(uint32_t*)&Ps[qw + (l >> 2)][cl]     = bf16x2(p00, p01);
            *(uint32_t*)&Ps[qw + 8 + (l >> 2)][cl] = bf16x2(p10, p11);
        }
        __syncthreads();

        // PV phase: warp accumulates 16q x 32d over this 64-k chunk
#pragma unroll
        for (int kk0 = 0; kk0 < 64; kk0 += 16) {
            uint32_t a[4];
            ldsm4(a, smem_u32(&Ps[qw + (l & 15)][kk0 + (l >> 4) * 8]));
#pragma unroll
            for (int ntp = 0; ntp < 2; ntp++) {
                uint32_t bfr[4];
                int krow = kk0 + (l & 7) + 8 * ((l >> 3) & 1);
                ldsm4t(bfr, smem_u32(&Vs[krow][dw + ntp * 16 + 8 * (l >> 4)]));
                mma_bf16(acc_pv[ntp * 2 + 0], a, bfr[0], bfr[1]);
                mma_bf16(acc_pv[ntp * 2 + 1], a, bfr[2], bfr[3]);
            }
        }
        __syncthreads();
    }

    // ctx epilogue
#pragma unroll
    for (int nt = 0; nt < 4; nt++) {
        int c = h * 64 + dw + nt * 8 + (l & 3) * 2;
        float2 w0 = {acc_pv[nt][0], acc_pv[nt][1]};
        float2 w1 = {acc_pv[nt][2], acc_pv[nt][3]};
        *(float2*)(g_ctx + (size_t)(bat * LL + r0g) * DMODEL + c) = w0;
        *(float2*)(g_ctx + (size_t)(bat * LL + r1g) * DMODEL + c) = w1;
    }
}

// =====================================================================
// Kernel 4: out = ctx @ Wo + bo + residual(q)
// =====================================================================
__global__ __launch_bounds__(256) void outproj_kernel(
    const float* __restrict__ resid, const float* __restrict__ Wo,
    const float* __restrict__ bo, float* __restrict__ out)
{
    __shared__ float As[16][128];
    __shared__ float Bs[16][128];

    const int col0 = blockIdx.x * 128;
    const int row0 = blockIdx.y * 128;
    const int t = threadIdx.x, tx = t & 15, ty = t >> 4;

    unsigned long long acc[8][4];
#pragma unroll
    for (int i = 0; i < 8; i++)
#pragma unroll
        for (int j = 0; j < 4; j++) acc[i][j] = 0ull;

    for (int k0 = 0; k0 < DMODEL; k0 += 16) {
#pragma unroll
        for (int p = 0; p < 2; p++) {
            int fi = t + p * 256;
            int k4 = fi & 3, row = fi >> 2;
            float4 fa = *(const float4*)(g_ctx + (size_t)(row0 + row) * DMODEL + k0 + k4 * 4);
            As[k4 * 4 + 0][row] = fa.x; As[k4 * 4 + 1][row] = fa.y;
            As[k4 * 4 + 2][row] = fa.z; As[k4 * 4 + 3][row] = fa.w;
            int c4 = fi & 31, kk = fi >> 5;
            float4 fb = *(const float4*)(Wo + (size_t)(k0 + kk) * DMODEL + col0 + c4 * 4);
            *(float4*)&Bs[kk][c4 * 4] = fb;
        }
        __syncthreads();
#pragma unroll
        for (int kk = 0; kk < 16; kk++) {
            float a[8];
            *(float4*)&a[0] = *(float4*)&As[kk][ty * 4];
            *(float4*)&a[4] = *(float4*)&As[kk][64 + ty * 4];
            ulonglong2 b0 = *(ulonglong2*)&Bs[kk][tx * 4];
            ulonglong2 b1 = *(ulonglong2*)&Bs[kk][64 + tx * 4];
            unsigned long long bp[4] = {b0.x, b0.y, b1.x, b1.y};
            unsigned long long ad[8];
#pragma unroll
            for (int i = 0; i < 8; i++) ad[i] = pack2(a[i]);
#pragma unroll
            for (int i = 0; i < 8; i++)
#pragma unroll
                for (int j = 0; j < 4; j++) ffma2(acc[i][j], ad[i], bp[j]);
        }
        __syncthreads();
    }

#pragma unroll
    for (int i = 0; i < 8; i++) {
        int row = row0 + ((i < 4) ? ty * 4 + i : 64 + ty * 4 + (i - 4));
#pragma unroll
        for (int jj = 0; jj < 2; jj++) {
            int cb = col0 + (jj ? 64 + tx * 4 : tx * 4);
            float4 rb = *(const float4*)(resid + (size_t)row * DMODEL + cb);
            float4 bb = *(const float4*)(bo + cb);
            float2 u0 = unpk(acc[i][jj * 2 + 0]);
            float2 u1 = unpk(acc[i][jj * 2 + 1]);
            float4 o;
            o.x = u0.x + bb.x + rb.x;
            o.y = u0.y + bb.y + rb.y;
            o.z = u1.x + bb.z + rb.z;
            o.w = u1.y + bb.w + rb.w;
            *(float4*)(out + (size_t)row * DMODEL + cb) = o;
        }
    }
}

// =====================================================================
extern "C" void kernel_launch(void* const* d_in, const int* in_sizes, int n_in,
                              void* d_out, int out_size)
{
    const float* q    = (const float*)d_in[0];
    const float* k    = (const float*)d_in[1];
    const float* v    = (const float*)d_in[2];
    const int*   mask = (const int*)  d_in[3];
    const float* Wq   = (const float*)d_in[4];
    const float* bq   = (const float*)d_in[5];
    const float* Wk   = (const float*)d_in[6];
    const float* bk   = (const float*)d_in[7];
    const float* Wv   = (const float*)d_in[8];
    const float* bv   = (const float*)d_in[9];
    const float* Wo   = (const float*)d_in[10];
    const float* bo   = (const float*)d_in[11];

    float* out  = (float*)d_out;
    float* attn = out + (size_t)NT * DMODEL;

    proj_kernel<<<dim3(4, 32, 3), 256>>>(q, k, v, Wq, bq, Wk, bk, Wv, bv);
    linv_kernel<<<dim3(32, 16), 256>>>(mask);
    pv2_kernel<<<dim3(32, 16), 256>>>(mask, attn);
    outproj_kernel<<<dim3(4, 32), 256>>>(q, Wo, bo, out);
}

// round 9
// speedup vs baseline: 2.2099x; 1.2745x over previous
#include <cuda_runtime.h>
#include <cuda_bf16.h>
#include <cstdint>

#define LL   2048
#define BB   2
#define DMODEL 512
#define HH   8
#define DKK  64
#define NT   4096   // BB*LL
#define HB   16     // HH*BB

// ---------------- scratch (device globals; no allocation allowed) ----------------
__device__ __nv_bfloat16 g_qhb[HB * LL * DKK];  // [hb][l][d] bf16, pre-scaled 1/64
__device__ __nv_bfloat16 g_khb[HB * LL * DKK];
__device__ __nv_bfloat16 g_vhb[HB * LL * DKK];
__device__ __nv_bfloat16 g_ctxbf[NT * DMODEL];  // ctx bf16 [b*L+l][h*64+d]
__device__ float g_linv[HB * LL];               // 1 / row sumexp

// ---------------- helpers ----------------
__device__ __forceinline__ uint32_t smem_u32(const void* p) {
    uint32_t a;
    asm("{ .reg .u64 t; cvta.to.shared.u64 t, %1; cvt.u32.u64 %0, t; }" : "=r"(a) : "l"(p));
    return a;
}
__device__ __forceinline__ uint32_t bf16x2(float lo, float hi) {
    uint32_t r;
    asm("cvt.rn.bf16x2.f32 %0, %1, %2;" : "=r"(r) : "f"(hi), "f"(lo));
    return r;
}
__device__ __forceinline__ void ldsm4(uint32_t* r, uint32_t addr) {
    asm volatile("ldmatrix.sync.aligned.m8n8.x4.shared.b16 {%0,%1,%2,%3}, [%4];"
                 : "=r"(r[0]), "=r"(r[1]), "=r"(r[2]), "=r"(r[3]) : "r"(addr));
}
__device__ __forceinline__ void ldsm4t(uint32_t* r, uint32_t addr) {
    asm volatile("ldmatrix.sync.aligned.m8n8.x4.trans.shared.b16 {%0,%1,%2,%3}, [%4];"
                 : "=r"(r[0]), "=r"(r[1]), "=r"(r[2]), "=r"(r[3]) : "r"(addr));
}
__device__ __forceinline__ void mma_bf16(float* c, const uint32_t* a, uint32_t b0, uint32_t b1) {
    asm volatile(
        "mma.sync.aligned.m16n8k16.row.col.f32.bf16.bf16.f32 "
        "{%0,%1,%2,%3}, {%4,%5,%6,%7}, {%8,%9}, {%0,%1,%2,%3};"
        : "+f"(c[0]), "+f"(c[1]), "+f"(c[2]), "+f"(c[3])
        : "r"(a[0]), "r"(a[1]), "r"(a[2]), "r"(a[3]), "r"(b0), "r"(b1));
}

// =====================================================================
// Kernel 1: fused QKV projection via bf16 mma.
// CTA: 64 rows x 128 cols, K in chunks of 64. 8 warps, 16m x 64n.
// =====================================================================
__global__ __launch_bounds__(256) void proj_kernel(
    const float* __restrict__ qin, const float* __restrict__ kin, const float* __restrict__ vin,
    const float* __restrict__ Wq, const float* __restrict__ bq,
    const float* __restrict__ Wk, const float* __restrict__ bk,
    const float* __restrict__ Wv, const float* __restrict__ bv)
{
    __shared__ __nv_bfloat16 As[64][72];    // X chunk, [m][k]
    __shared__ __nv_bfloat16 Ws[64][136];   // W chunk, [k][n]

    const int z = blockIdx.z;
    const float* X    = (z == 0) ? qin : (z == 1) ? kin : vin;
    const float* W    = (z == 0) ? Wq  : (z == 1) ? Wk  : Wv;
    const float* bias = (z == 0) ? bq  : (z == 1) ? bk  : bv;
    __nv_bfloat16* outp = (z == 0) ? g_qhb : (z == 1) ? g_khb : g_vhb;
    const float scale = (z == 0) ? (1.0f / 64.0f) : 1.0f;

    const int row0 = blockIdx.y * 64;
    const int col0 = blockIdx.x * 128;
    const int t = threadIdx.x, w = t >> 5, l = t & 31;
    const int qw = (w >> 1) * 16;
    const int nw = (w & 1) * 64;

    float acc[8][4];
#pragma unroll
    for (int nt = 0; nt < 8; nt++)
#pragma unroll
        for (int e = 0; e < 4; e++) acc[nt][e] = 0.0f;

    for (int k0 = 0; k0 < DMODEL; k0 += 64) {
        // stage A: 64x64 X fp32 -> bf16
#pragma unroll
        for (int p = 0; p < 4; p++) {
            int fi = t + p * 256;
            int row = fi >> 4, c4 = fi & 15;
            float4 f = *(const float4*)(X + (size_t)(row0 + row) * DMODEL + k0 + c4 * 4);
            uint2 pk = {bf16x2(f.x, f.y), bf16x2(f.z, f.w)};
            *(uint2*)&As[row][c4 * 4] = pk;
        }
        // stage B: 64k x 128n W fp32 -> bf16
#pragma unroll
        for (int p = 0; p < 8; p++) {
            int fi = t + p * 256;
            int krow = fi >> 5, c4 = fi & 31;
            float4 f = *(const float4*)(W + (size_t)(k0 + krow) * DMODEL + col0 + c4 * 4);
            uint2 pk = {bf16x2(f.x, f.y), bf16x2(f.z, f.w)};
            *(uint2*)&Ws[krow][c4 * 4] = pk;
        }
        __syncthreads();

#pragma unroll
        for (int d0 = 0; d0 < 64; d0 += 16) {
            uint32_t a[4];
            ldsm4(a, smem_u32(&As[qw + (l & 15)][d0 + (l >> 4) * 8]));
#pragma unroll
            for (int ntp = 0; ntp < 4; ntp++) {
                uint32_t bfr[4];
                int krow = d0 + (l & 7) + 8 * ((l >> 3) & 1);
                ldsm4t(bfr, smem_u32(&Ws[krow][nw + ntp * 16 + 8 * (l >> 4)]));
                mma_bf16(acc[ntp * 2 + 0], a, bfr[0], bfr[1]);
                mma_bf16(acc[ntp * 2 + 1], a, bfr[2], bfr[3]);
            }
        }
        __syncthreads();
    }

    // epilogue: +bias, *scale, write bf16 into [hb][l][d]
    const int r0 = row0 + qw + (l >> 2);
    const int r1 = r0 + 8;
#pragma unroll
    for (int nt = 0; nt < 8; nt++) {
        int cg = col0 + nw + nt * 8 + (l & 3) * 2;
        int h = cg >> 6, d = cg & 63;
        float b0 = bias[cg], b1 = bias[cg + 1];
        float o00 = (acc[nt][0] + b0) * scale;
        float o01 = (acc[nt][1] + b1) * scale;
        float o10 = (acc[nt][2] + b0) * scale;
        float o11 = (acc[nt][3] + b1) * scale;
        *(uint32_t*)(outp + (size_t)((h * BB + (r0 >> 11)) * LL + (r0 & 2047)) * DKK + d) = bf16x2(o00, o01);
        *(uint32_t*)(outp + (size_t)((h * BB + (r1 >> 11)) * LL + (r1 & 2047)) * DKK + d) = bf16x2(o10, o11);
    }
}

// =====================================================================
// Kernel 2: pass 1 — row sums of exp(S) in registers -> g_linv.
// =====================================================================
__global__ __launch_bounds__(256) void linv_kernel(const int* __restrict__ mask)
{
    __shared__ __nv_bfloat16 Qs[64][72];
    __shared__ __nv_bfloat16 Ks[128][72];
    __shared__ float sred[2][64];

    const int hb = blockIdx.y;
    const int q0 = blockIdx.x * 64;
    const int bat = hb & 1;
    const int t = threadIdx.x, w = t >> 5, l = t & 31;
    const int qw = (w >> 1) * 16;
    const int kwsel = w & 1;
    const int kw = kwsel * 64;

    const __nv_bfloat16* qb = g_qhb + (size_t)hb * LL * DKK + (size_t)q0 * DKK;
    const __nv_bfloat16* kb = g_khb + (size_t)hb * LL * DKK;
    const int* mb = mask + (size_t)bat * LL * LL;

#pragma unroll
    for (int p = 0; p < 2; p++) {
        int fi = t + p * 256;
        int row = fi >> 3, c8 = fi & 7;
        *(uint4*)&Qs[row][c8 * 8] = *(const uint4*)(qb + (size_t)row * DKK + c8 * 8);
    }

    float rs0 = 0.0f, rs1 = 0.0f;
    const int r0g = q0 + qw + (l >> 2);
    const int r1g = r0g + 8;

    for (int kt = 0; kt < 16; kt++) {
        const int k0 = kt * 128;
#pragma unroll
        for (int p = 0; p < 4; p++) {
            int fi = t + p * 256;
            int row = fi >> 3, c8 = fi & 7;
            *(uint4*)&Ks[row][c8 * 8] = *(const uint4*)(kb + (size_t)(k0 + row) * DKK + c8 * 8);
        }
        __syncthreads();

        float acc[8][4];
#pragma unroll
        for (int nt = 0; nt < 8; nt++)
#pragma unroll
            for (int e = 0; e < 4; e++) acc[nt][e] = 0.0f;

#pragma unroll
        for (int d0 = 0; d0 < 64; d0 += 16) {
            uint32_t a[4];
            ldsm4(a, smem_u32(&Qs[qw + (l & 15)][d0 + (l >> 4) * 8]));
#pragma unroll
            for (int ntp = 0; ntp < 4; ntp++) {
                uint32_t bfr[4];
                int nrow = kw + ntp * 16 + (l & 7) + 8 * (l >> 4);
                ldsm4(bfr, smem_u32(&Ks[nrow][d0 + 8 * ((l >> 3) & 1)]));
                mma_bf16(acc[ntp * 2 + 0], a, bfr[0], bfr[1]);
                mma_bf16(acc[ntp * 2 + 1], a, bfr[2], bfr[3]);
            }
        }

#pragma unroll
        for (int nt = 0; nt < 8; nt++) {
            int c = k0 + kw + nt * 8 + (l & 3) * 2;
            int2 m0 = *(const int2*)(mb + (size_t)r0g * LL + c);
            int2 m1 = *(const int2*)(mb + (size_t)r1g * LL + c);
            rs0 += (m0.x ? __expf(acc[nt][0]) : 0.0f) + (m0.y ? __expf(acc[nt][1]) : 0.0f);
            rs1 += (m1.x ? __expf(acc[nt][2]) : 0.0f) + (m1.y ? __expf(acc[nt][3]) : 0.0f);
        }
        __syncthreads();
    }

    rs0 += __shfl_xor_sync(0xffffffffu, rs0, 1);
    rs0 += __shfl_xor_sync(0xffffffffu, rs0, 2);
    rs1 += __shfl_xor_sync(0xffffffffu, rs1, 1);
    rs1 += __shfl_xor_sync(0xffffffffu, rs1, 2);
    if ((l & 3) == 0) {
        sred[kwsel][qw + (l >> 2)]     = rs0;
        sred[kwsel][qw + 8 + (l >> 2)] = rs1;
    }
    __syncthreads();
    if (t < 64)
        g_linv[hb * LL + q0 + t] = 1.0f / (sred[0][t] + sred[1][t]);
}

// =====================================================================
// Kernel 3: pass 2 — recompute S, P = mask*exp(S)*linv (write attn),
// accumulate ctx = P @ V (bf16 out).
// =====================================================================
__global__ __launch_bounds__(256) void pv2_kernel(const int* __restrict__ mask,
                                                  float* __restrict__ attn)
{
    __shared__ __nv_bfloat16 Qs[64][72];
    __shared__ __nv_bfloat16 Ks[64][72];
    __shared__ __nv_bfloat16 Vs[64][72];
    __shared__ __nv_bfloat16 Ps[64][72];

    const int hb = blockIdx.y;
    const int q0 = blockIdx.x * 64;
    const int bat = hb & 1;
    const int h = hb >> 1;
    const int t = threadIdx.x, w = t >> 5, l = t & 31;
    const int qw = (w >> 1) * 16;
    const int kw = (w & 1) * 32;
    const int dw = (w & 1) * 32;

    const __nv_bfloat16* qb = g_qhb + (size_t)hb * LL * DKK + (size_t)q0 * DKK;
    const __nv_bfloat16* kb = g_khb + (size_t)hb * LL * DKK;
    const __nv_bfloat16* vb = g_vhb + (size_t)hb * LL * DKK;
    const int* mb = mask + (size_t)bat * LL * LL;
    float* ab = attn + (size_t)hb * LL * LL;

#pragma unroll
    for (int p = 0; p < 2; p++) {
        int fi = t + p * 256;
        int row = fi >> 3, c8 = fi & 7;
        *(uint4*)&Qs[row][c8 * 8] = *(const uint4*)(qb + (size_t)row * DKK + c8 * 8);
    }

    const int r0g = q0 + qw + (l >> 2);
    const int r1g = r0g + 8;
    const float li0 = g_linv[hb * LL + r0g];
    const float li1 = g_linv[hb * LL + r1g];

    float acc_pv[4][4];
#pragma unroll
    for (int nt = 0; nt < 4; nt++)
#pragma unroll
        for (int e = 0; e < 4; e++) acc_pv[nt][e] = 0.0f;

    for (int s = 0; s < 32; s++) {
        const int k0 = s * 64;
#pragma unroll
        for (int p = 0; p < 2; p++) {
            int fi = t + p * 256;
            int row = fi >> 3, c8 = fi & 7;
            *(uint4*)&Ks[row][c8 * 8] = *(const uint4*)(kb + (size_t)(k0 + row) * DKK + c8 * 8);
            *(uint4*)&Vs[row][c8 * 8] = *(const uint4*)(vb + (size_t)(k0 + row) * DKK + c8 * 8);
        }
        __syncthreads();

        float acc_s[4][4];
#pragma unroll
        for (int nt = 0; nt < 4; nt++)
#pragma unroll
            for (int e = 0; e < 4; e++) acc_s[nt][e] = 0.0f;

#pragma unroll
        for (int d0 = 0; d0 < 64; d0 += 16) {
            uint32_t a[4];
            ldsm4(a, smem_u32(&Qs[qw + (l & 15)][d0 + (l >> 4) * 8]));
#pragma unroll
            for (int ntp = 0; ntp < 2; ntp++) {
                uint32_t bfr[4];
                int nrow = kw + ntp * 16 + (l & 7) + 8 * (l >> 4);
                ldsm4(bfr, smem_u32(&Ks[nrow][d0 + 8 * ((l >> 3) & 1)]));
                mma_bf16(acc_s[ntp * 2 + 0], a, bfr[0], bfr[1]);
                mma_bf16(acc_s[ntp * 2 + 1], a, bfr[2], bfr[3]);
            }
        }

#pragma unroll
        for (int nt = 0; nt < 4; nt++) {
            int cl = kw + nt * 8 + (l & 3) * 2;
            int c = k0 + cl;
            int2 m0 = *(const int2*)(mb + (size_t)r0g * LL + c);
            int2 m1 = *(const int2*)(mb + (size_t)r1g * LL + c);
            float p00 = m0.x ? __expf(acc_s[nt][0]) * li0 : 0.0f;
            float p01 = m0.y ? __expf(acc_s[nt][1]) * li0 : 0.0f;
            float p10 = m1.x ? __expf(acc_s[nt][2]) * li1 : 0.0f;
            float p11 = m1.y ? __expf(acc_s[nt][3]) * li1 : 0.0f;
            float2 w0 = {p00, p01}, w1 = {p10, p11};
            *(float2*)(ab + (size_t)r0g * LL + c) = w0;
            *(float2*)(ab + (size_t)r1g * LL + c) = w1;
            *(uint32_t*)&Ps[qw + (l >> 2)][cl]     = bf16x2(p00, p01);
            *(uint32_t*)&Ps[qw + 8 + (l >> 2)][cl] = bf16x2(p10, p11);
        }
        __syncthreads();

#pragma unroll
        for (int kk0 = 0; kk0 < 64; kk0 += 16) {
            uint32_t a[4];
            ldsm4(a, smem_u32(&Ps[qw + (l & 15)][kk0 + (l >> 4) * 8]));
#pragma unroll
            for (int ntp = 0; ntp < 2; ntp++) {
                uint32_t bfr[4];
                int krow = kk0 + (l & 7) + 8 * ((l >> 3) & 1);
                ldsm4t(bfr, smem_u32(&Vs[krow][dw + ntp * 16 + 8 * (l >> 4)]));
                mma_bf16(acc_pv[ntp * 2 + 0], a, bfr[0], bfr[1]);
                mma_bf16(acc_pv[ntp * 2 + 1], a, bfr[2], bfr[3]);
            }
        }
        __syncthreads();
    }

    // ctx epilogue (bf16)
#pragma unroll
    for (int nt = 0; nt < 4; nt++) {
        int c = h * 64 + dw + nt * 8 + (l & 3) * 2;
        *(uint32_t*)(g_ctxbf + (size_t)(bat * LL + r0g) * DMODEL + c) = bf16x2(acc_pv[nt][0], acc_pv[nt][1]);
        *(uint32_t*)(g_ctxbf + (size_t)(bat * LL + r1g) * DMODEL + c) = bf16x2(acc_pv[nt][2], acc_pv[nt][3]);
    }
}

// =====================================================================
// Kernel 4: out = ctx(bf16) @ Wo + bo + residual(q), bf16 mma.
// CTA: 64 rows x 128 cols. grid (4, 64).
// =====================================================================
__global__ __launch_bounds__(256) void outproj_kernel(
    const float* __restrict__ resid, const float* __restrict__ Wo,
    const float* __restrict__ bo, float* __restrict__ out)
{
    __shared__ __nv_bfloat16 As[64][72];
    __shared__ __nv_bfloat16 Ws[64][136];

    const int row0 = blockIdx.y * 64;
    const int col0 = blockIdx.x * 128;
    const int t = threadIdx.x, w = t >> 5, l = t & 31;
    const int qw = (w >> 1) * 16;
    const int nw = (w & 1) * 64;

    float acc[8][4];
#pragma unroll
    for (int nt = 0; nt < 8; nt++)
#pragma unroll
        for (int e = 0; e < 4; e++) acc[nt][e] = 0.0f;

    for (int k0 = 0; k0 < DMODEL; k0 += 64) {
        // stage A: ctx bf16 direct
#pragma unroll
        for (int p = 0; p < 2; p++) {
            int fi = t + p * 256;
            int row = fi >> 3, c8 = fi & 7;
            *(uint4*)&As[row][c8 * 8] =
                *(const uint4*)(g_ctxbf + (size_t)(row0 + row) * DMODEL + k0 + c8 * 8);
        }
        // stage B: Wo fp32 -> bf16
#pragma unroll
        for (int p = 0; p < 8; p++) {
            int fi = t + p * 256;
            int krow = fi >> 5, c4 = fi & 31;
            float4 f = *(const float4*)(Wo + (size_t)(k0 + krow) * DMODEL + col0 + c4 * 4);
            uint2 pk = {bf16x2(f.x, f.y), bf16x2(f.z, f.w)};
            *(uint2*)&Ws[krow][c4 * 4] = pk;
        }
        __syncthreads();

#pragma unroll
        for (int d0 = 0; d0 < 64; d0 += 16) {
            uint32_t a[4];
            ldsm4(a, smem_u32(&As[qw + (l & 15)][d0 + (l >> 4) * 8]));
#pragma unroll
            for (int ntp = 0; ntp < 4; ntp++) {
                uint32_t bfr[4];
                int krow = d0 + (l & 7) + 8 * ((l >> 3) & 1);
                ldsm4t(bfr, smem_u32(&Ws[krow][nw + ntp * 16 + 8 * (l >> 4)]));
                mma_bf16(acc[ntp * 2 + 0], a, bfr[0], bfr[1]);
                mma_bf16(acc[ntp * 2 + 1], a, bfr[2], bfr[3]);
            }
        }
        __syncthreads();
    }

    const int r0 = row0 + qw + (l >> 2);
    const int r1 = r0 + 8;
#pragma unroll
    for (int nt = 0; nt < 8; nt++) {
        int cg = col0 + nw + nt * 8 + (l & 3) * 2;
        float b0 = bo[cg], b1 = bo[cg + 1];
        float2 x0 = *(const float2*)(resid + (size_t)r0 * DMODEL + cg);
        float2 x1 = *(const float2*)(resid + (size_t)r1 * DMODEL + cg);
        float2 o0 = {acc[nt][0] + b0 + x0.x, acc[nt][1] + b1 + x0.y};
        float2 o1 = {acc[nt][2] + b0 + x1.x, acc[nt][3] + b1 + x1.y};
        *(float2*)(out + (size_t)r0 * DMODEL + cg) = o0;
        *(float2*)(out + (size_t)r1 * DMODEL + cg) = o1;
    }
}

// =====================================================================
extern "C" void kernel_launch(void* const* d_in, const int* in_sizes, int n_in,
                              void* d_out, int out_size)
{
    const float* q    = (const float*)d_in[0];
    const float* k    = (const float*)d_in[1];
    const float* v    = (const float*)d_in[2];
    const int*   mask = (const int*)  d_in[3];
    const float* Wq   = (const float*)d_in[4];
    const float* bq   = (const float*)d_in[5];
    const float* Wk   = (const float*)d_in[6];
    const float* bk   = (const float*)d_in[7];
    const float* Wv   = (const float*)d_in[8];
    const float* bv   = (const float*)d_in[9];
    const float* Wo   = (const float*)d_in[10];
    const float* bo   = (const float*)d_in[11];

    float* out  = (float*)d_out;
    float* attn = out + (size_t)NT * DMODEL;

    proj_kernel<<<dim3(4, 64, 3), 256>>>(q, k, v, Wq, bq, Wk, bk, Wv, bv);
    linv_kernel<<<dim3(32, 16), 256>>>(mask);
    pv2_kernel<<<dim3(32, 16), 256>>>(mask, attn);
    outproj_kernel<<<dim3(4, 64), 256>>>(q, Wo, bo, out);
}